// round 6
// baseline (speedup 1.0000x reference)
#include <cuda_runtime.h>
#include <math.h>
#include <stdint.h>

#define T_SEQ 4096
#define C_MODEL 1024
#define NHEADS 16
#define DHEAD 64

// Scratch (allocation-free rule: __device__ globals)
__device__ float g_q[T_SEQ * C_MODEL];
__device__ float g_k[T_SEQ * C_MODEL];
__device__ float g_v[T_SEQ * C_MODEL];
__device__ float g_attn[T_SEQ * C_MODEL];

__device__ __forceinline__ uint32_t f2tf32(float x) {
  uint32_t r;
  asm("cvt.rna.tf32.f32 %0, %1;" : "=r"(r) : "f"(x));
  return r;
}

__device__ __forceinline__ void mma_tf32(float* d, const uint32_t* a,
                                         const uint32_t* b) {
  asm volatile(
      "mma.sync.aligned.m16n8k8.row.col.f32.tf32.tf32.f32 "
      "{%0,%1,%2,%3}, {%4,%5,%6,%7}, {%8,%9}, {%0,%1,%2,%3};\n"
      : "+f"(d[0]), "+f"(d[1]), "+f"(d[2]), "+f"(d[3])
      : "r"(a[0]), "r"(a[1]), "r"(a[2]), "r"(a[3]), "r"(b[0]), "r"(b[1]));
}

// ---------------------------------------------------------------------------
// C[M,N] = A[M,K] @ B[N,K]^T + bias[N]   (tf32 tensor cores)
// CTA tile 128x128, BK=32, 256 threads = 8 warps in 2(m) x 4(n).
// Warp tile 64x32 -> 4x4 grid of m16n8k8 mma.
// Smem pitch 36 floats: fragment LDS pattern is bank = lane (conflict-free),
// and float4 staging stores are conflict-free as well.
// ---------------------------------------------------------------------------
#define TPITCH 36

__global__ __launch_bounds__(256) void gemm_bias_tc(
    const float* __restrict__ A, const float* __restrict__ B,
    const float* __restrict__ bias, float* __restrict__ Cout,
    int M, int N, int K) {
  __shared__ uint32_t As[128][TPITCH];
  __shared__ uint32_t Bs[128][TPITCH];

  const int tid = threadIdx.x;
  const int lane = tid & 31;
  const int wid = tid >> 5;
  const int wm = wid >> 2;          // 0..1
  const int wn = wid & 3;           // 0..3
  const int l4 = lane >> 2;         // 0..7
  const int lm4 = lane & 3;         // 0..3
  const int bm = blockIdx.y * 128;
  const int bn = blockIdx.x * 128;

  const int srow = tid >> 1;            // 0..127
  const int scol = (tid & 1) * 16;      // 0 or 16

  float acc[4][4][4];
#pragma unroll
  for (int i = 0; i < 4; i++)
#pragma unroll
    for (int j = 0; j < 4; j++)
#pragma unroll
      for (int c = 0; c < 4; c++) acc[i][j][c] = 0.f;

  const float* Aptr = A + (bm + srow) * K + scol;
  const float* Bptr = B + (bn + srow) * K + scol;

  // prefetch first tile
  float4 pa[4], pb[4];
#pragma unroll
  for (int i = 0; i < 4; i++) {
    pa[i] = *(const float4*)(Aptr + i * 4);
    pb[i] = *(const float4*)(Bptr + i * 4);
  }

  for (int k0 = 0; k0 < K; k0 += 32) {
    __syncthreads();
#pragma unroll
    for (int i = 0; i < 4; i++) {
      uint32_t* ad = &As[srow][scol + i * 4];
      ad[0] = f2tf32(pa[i].x); ad[1] = f2tf32(pa[i].y);
      ad[2] = f2tf32(pa[i].z); ad[3] = f2tf32(pa[i].w);
      uint32_t* bd = &Bs[srow][scol + i * 4];
      bd[0] = f2tf32(pb[i].x); bd[1] = f2tf32(pb[i].y);
      bd[2] = f2tf32(pb[i].z); bd[3] = f2tf32(pb[i].w);
    }
    __syncthreads();

    if (k0 + 32 < K) {  // prefetch next tile (overlaps with mma below)
#pragma unroll
      for (int i = 0; i < 4; i++) {
        pa[i] = *(const float4*)(Aptr + k0 + 32 + i * 4);
        pb[i] = *(const float4*)(Bptr + k0 + 32 + i * 4);
      }
    }

#pragma unroll
    for (int kk = 0; kk < 4; kk++) {
      uint32_t af[4][4], bf[4][2];
#pragma unroll
      for (int i = 0; i < 4; i++) {
        const int r = wm * 64 + i * 16 + l4;
        af[i][0] = As[r][kk * 8 + lm4];
        af[i][1] = As[r + 8][kk * 8 + lm4];
        af[i][2] = As[r][kk * 8 + lm4 + 4];
        af[i][3] = As[r + 8][kk * 8 + lm4 + 4];
      }
#pragma unroll
      for (int j = 0; j < 4; j++) {
        const int n = wn * 32 + j * 8 + l4;
        bf[j][0] = Bs[n][kk * 8 + lm4];
        bf[j][1] = Bs[n][kk * 8 + lm4 + 4];
      }
#pragma unroll
      for (int i = 0; i < 4; i++)
#pragma unroll
        for (int j = 0; j < 4; j++) mma_tf32(acc[i][j], af[i], bf[j]);
    }
  }

  // Epilogue: D rows bm + wm*64 + i*16 + l4 (+8); cols bn + wn*32 + j*8 + lm4*2 (+1)
#pragma unroll
  for (int j = 0; j < 4; j++) {
    const int c = bn + wn * 32 + j * 8 + lm4 * 2;
    const float bi0 = bias[c], bi1 = bias[c + 1];
#pragma unroll
    for (int i = 0; i < 4; i++) {
      const int r = bm + wm * 64 + i * 16 + l4;
      float2 o0 = make_float2(acc[i][j][0] + bi0, acc[i][j][1] + bi1);
      float2 o1 = make_float2(acc[i][j][2] + bi0, acc[i][j][3] + bi1);
      *(float2*)(Cout + r * N + c) = o0;
      *(float2*)(Cout + (r + 8) * N + c) = o1;
    }
  }
}

// ---------------------------------------------------------------------------
// Causal flash attention, fp32, gemm-style tiling (unchanged from R4 pass).
// ---------------------------------------------------------------------------
#define BM 128
#define BN 128
#define AD 64
#define PQ 132
#define PVP 68
#define PP 132

#define ATTN_SMEM ((2 * AD * PQ + BN * PVP + BM * PP) * sizeof(float))

__global__ __launch_bounds__(256) void flash_attn2(
    const float* __restrict__ Q, const float* __restrict__ K,
    const float* __restrict__ V, float* __restrict__ O) {
  extern __shared__ float sm[];
  float* Qs = sm;
  float* Ks = Qs + AD * PQ;
  float* Vs = Ks + AD * PQ;
  float* Ps = Vs + BN * PVP;

  const int qb = gridDim.x - 1 - blockIdx.x;
  const int h  = blockIdx.y;
  const int tid = threadIdx.x;
  const int ty = tid >> 4;
  const int tx = tid & 15;
  const float scale2 = 0.125f * 1.44269504088896f;

  {
    const int r = tid >> 1;
    const int cb = (tid & 1) * 32;
    const float* src = Q + (qb * BM + r) * C_MODEL + h * AD + cb;
#pragma unroll
    for (int i = 0; i < 8; i++) {
      float4 v4 = *(const float4*)(src + i * 4);
      Qs[(cb + i * 4 + 0) * PQ + r] = v4.x;
      Qs[(cb + i * 4 + 1) * PQ + r] = v4.y;
      Qs[(cb + i * 4 + 2) * PQ + r] = v4.z;
      Qs[(cb + i * 4 + 3) * PQ + r] = v4.w;
    }
  }

  float m_i[8], l_i[8], Oacc[8][4];
#pragma unroll
  for (int a = 0; a < 8; a++) {
    m_i[a] = -1e30f; l_i[a] = 0.f;
#pragma unroll
    for (int c = 0; c < 4; c++) Oacc[a][c] = 0.f;
  }

  for (int kt = 0; kt <= qb; kt++) {
    __syncthreads();
    {
      const int r = tid >> 1;
      const int cb = (tid & 1) * 32;
      const float* ks = K + (kt * BN + r) * C_MODEL + h * AD + cb;
      const float* vs = V + (kt * BN + r) * C_MODEL + h * AD + cb;
#pragma unroll
      for (int i = 0; i < 8; i++) {
        float4 kv = *(const float4*)(ks + i * 4);
        Ks[(cb + i * 4 + 0) * PQ + r] = kv.x;
        Ks[(cb + i * 4 + 1) * PQ + r] = kv.y;
        Ks[(cb + i * 4 + 2) * PQ + r] = kv.z;
        Ks[(cb + i * 4 + 3) * PQ + r] = kv.w;
        *(float4*)&Vs[r * PVP + cb + i * 4] = *(const float4*)(vs + i * 4);
      }
    }
    __syncthreads();

    float s[8][8];
#pragma unroll
    for (int a = 0; a < 8; a++)
#pragma unroll
      for (int j = 0; j < 8; j++) s[a][j] = 0.f;
#pragma unroll 4
    for (int k = 0; k < AD; k++) {
      float a[8], b[8];
      *(float4*)&a[0] = *(const float4*)&Qs[k * PQ + ty * 8 + 0];
      *(float4*)&a[4] = *(const float4*)&Qs[k * PQ + ty * 8 + 4];
      *(float4*)&b[0] = *(const float4*)&Ks[k * PQ + tx * 8 + 0];
      *(float4*)&b[4] = *(const float4*)&Ks[k * PQ + tx * 8 + 4];
#pragma unroll
      for (int i = 0; i < 8; i++)
#pragma unroll
        for (int j = 0; j < 8; j++) s[i][j] = fmaf(a[i], b[j], s[i][j]);
    }

    if (kt == qb) {
#pragma unroll
      for (int a = 0; a < 8; a++)
#pragma unroll
        for (int j = 0; j < 8; j++)
          s[a][j] = (tx * 8 + j) > (ty * 8 + a) ? -1e30f : s[a][j] * scale2;
    } else {
#pragma unroll
      for (int a = 0; a < 8; a++)
#pragma unroll
        for (int j = 0; j < 8; j++) s[a][j] *= scale2;
    }

#pragma unroll
    for (int a = 0; a < 8; a++) {
      float rm = s[a][0];
#pragma unroll
      for (int j = 1; j < 8; j++) rm = fmaxf(rm, s[a][j]);
#pragma unroll
      for (int off = 8; off > 0; off >>= 1)
        rm = fmaxf(rm, __shfl_xor_sync(0xffffffffu, rm, off));
      const float mnew = fmaxf(m_i[a], rm);
      const float alpha = exp2f(m_i[a] - mnew);
      float rs = 0.f;
#pragma unroll
      for (int j = 0; j < 8; j++) {
        const float p = exp2f(s[a][j] - mnew);
        s[a][j] = p;
        rs += p;
      }
#pragma unroll
      for (int off = 8; off > 0; off >>= 1)
        rs += __shfl_xor_sync(0xffffffffu, rs, off);
      l_i[a] = l_i[a] * alpha + rs;
      m_i[a] = mnew;
#pragma unroll
      for (int c = 0; c < 4; c++) Oacc[a][c] *= alpha;
      float4 p0 = make_float4(s[a][0], s[a][1], s[a][2], s[a][3]);
      float4 p1 = make_float4(s[a][4], s[a][5], s[a][6], s[a][7]);
      *(float4*)&Ps[(ty * 8 + a) * PP + tx * 8 + 0] = p0;
      *(float4*)&Ps[(ty * 8 + a) * PP + tx * 8 + 4] = p1;
    }
    __syncthreads();

#pragma unroll 2
    for (int j0 = 0; j0 < BN; j0 += 4) {
      float4 vr[4];
#pragma unroll
      for (int jj = 0; jj < 4; jj++)
        vr[jj] = *(const float4*)&Vs[(j0 + jj) * PVP + tx * 4];
#pragma unroll
      for (int a = 0; a < 8; a++) {
        float4 p4 = *(const float4*)&Ps[(ty * 8 + a) * PP + j0];
        Oacc[a][0] = fmaf(p4.x, vr[0].x, Oacc[a][0]);
        Oacc[a][1] = fmaf(p4.x, vr[0].y, Oacc[a][1]);
        Oacc[a][2] = fmaf(p4.x, vr[0].z, Oacc[a][2]);
        Oacc[a][3] = fmaf(p4.x, vr[0].w, Oacc[a][3]);
        Oacc[a][0] = fmaf(p4.y, vr[1].x, Oacc[a][0]);
        Oacc[a][1] = fmaf(p4.y, vr[1].y, Oacc[a][1]);
        Oacc[a][2] = fmaf(p4.y, vr[1].z, Oacc[a][2]);
        Oacc[a][3] = fmaf(p4.y, vr[1].w, Oacc[a][3]);
        Oacc[a][0] = fmaf(p4.z, vr[2].x, Oacc[a][0]);
        Oacc[a][1] = fmaf(p4.z, vr[2].y, Oacc[a][1]);
        Oacc[a][2] = fmaf(p4.z, vr[2].z, Oacc[a][2]);
        Oacc[a][3] = fmaf(p4.z, vr[2].w, Oacc[a][3]);
        Oacc[a][0] = fmaf(p4.w, vr[3].x, Oacc[a][0]);
        Oacc[a][1] = fmaf(p4.w, vr[3].y, Oacc[a][1]);
        Oacc[a][2] = fmaf(p4.w, vr[3].z, Oacc[a][2]);
        Oacc[a][3] = fmaf(p4.w, vr[3].w, Oacc[a][3]);
      }
    }
  }

#pragma unroll
  for (int a = 0; a < 8; a++) {
    const float inv = 1.f / l_i[a];
    const int r = qb * BM + ty * 8 + a;
    float4 o;
    o.x = Oacc[a][0] * inv;
    o.y = Oacc[a][1] * inv;
    o.z = Oacc[a][2] * inv;
    o.w = Oacc[a][3] * inv;
    *(float4*)(O + r * C_MODEL + h * AD + tx * 4) = o;
  }
}

// ---------------------------------------------------------------------------
extern "C" void kernel_launch(void* const* d_in, const int* in_sizes, int n_in,
                              void* d_out, int out_size) {
  const float* x  = (const float*)d_in[0];
  const float* Wq = (const float*)d_in[1];
  const float* bq = (const float*)d_in[2];
  const float* Wk = (const float*)d_in[3];
  const float* bk = (const float*)d_in[4];
  const float* Wv = (const float*)d_in[5];
  const float* bv = (const float*)d_in[6];
  const float* Wo = (const float*)d_in[7];
  const float* bo = (const float*)d_in[8];
  float* out = (float*)d_out;

  float *qp, *kp, *vp, *ap;
  cudaGetSymbolAddress((void**)&qp, g_q);
  cudaGetSymbolAddress((void**)&kp, g_k);
  cudaGetSymbolAddress((void**)&vp, g_v);
  cudaGetSymbolAddress((void**)&ap, g_attn);

  cudaFuncSetAttribute(flash_attn2, cudaFuncAttributeMaxDynamicSharedMemorySize,
                       (int)ATTN_SMEM);

  dim3 gb(C_MODEL / 128, T_SEQ / 128);  // (8, 32)
  gemm_bias_tc<<<gb, 256>>>(x, Wq, bq, qp, T_SEQ, C_MODEL, C_MODEL);
  gemm_bias_tc<<<gb, 256>>>(x, Wk, bk, kp, T_SEQ, C_MODEL, C_MODEL);
  gemm_bias_tc<<<gb, 256>>>(x, Wv, bv, vp, T_SEQ, C_MODEL, C_MODEL);

  dim3 ga(T_SEQ / BM, NHEADS);          // (32, 16)
  flash_attn2<<<ga, 256, ATTN_SMEM>>>(qp, kp, vp, ap);

  gemm_bias_tc<<<gb, 256>>>(ap, Wo, bo, out, T_SEQ, C_MODEL, C_MODEL);
}

// round 8
// speedup vs baseline: 1.8334x; 1.8334x over previous
#include <cuda_runtime.h>
#include <math.h>
#include <stdint.h>

#define T_SEQ 4096
#define C_MODEL 1024
#define NHEADS 16
#define DHEAD 64

// Scratch (allocation-free rule: __device__ globals)
__device__ float g_q[T_SEQ * C_MODEL];
__device__ float g_k[T_SEQ * C_MODEL];
__device__ float g_v[T_SEQ * C_MODEL];
__device__ float g_attn[T_SEQ * C_MODEL];

__device__ __forceinline__ uint32_t f2tf32(float x) {
  uint32_t r;
  asm("cvt.rna.tf32.f32 %0, %1;" : "=r"(r) : "f"(x));
  return r;
}

__device__ __forceinline__ void mma_tf32(float* d, const uint32_t* a,
                                         const uint32_t* b) {
  asm volatile(
      "mma.sync.aligned.m16n8k8.row.col.f32.tf32.tf32.f32 "
      "{%0,%1,%2,%3}, {%4,%5,%6,%7}, {%8,%9}, {%0,%1,%2,%3};\n"
      : "+f"(d[0]), "+f"(d[1]), "+f"(d[2]), "+f"(d[3])
      : "r"(a[0]), "r"(a[1]), "r"(a[2]), "r"(a[3]), "r"(b[0]), "r"(b[1]));
}

// ---------------------------------------------------------------------------
// C[M,N] = A[M,K] @ B[N,K]^T + bias[N]   (tf32 tensor cores) — unchanged R6.
// ---------------------------------------------------------------------------
#define TPITCH 36

__global__ __launch_bounds__(256) void gemm_bias_tc(
    const float* __restrict__ A, const float* __restrict__ B,
    const float* __restrict__ bias, float* __restrict__ Cout,
    int M, int N, int K) {
  __shared__ uint32_t As[128][TPITCH];
  __shared__ uint32_t Bs[128][TPITCH];

  const int tid = threadIdx.x;
  const int lane = tid & 31;
  const int wid = tid >> 5;
  const int wm = wid >> 2;
  const int wn = wid & 3;
  const int l4 = lane >> 2;
  const int lm4 = lane & 3;
  const int bm = blockIdx.y * 128;
  const int bn = blockIdx.x * 128;

  const int srow = tid >> 1;
  const int scol = (tid & 1) * 16;

  float acc[4][4][4];
#pragma unroll
  for (int i = 0; i < 4; i++)
#pragma unroll
    for (int j = 0; j < 4; j++)
#pragma unroll
      for (int c = 0; c < 4; c++) acc[i][j][c] = 0.f;

  const float* Aptr = A + (bm + srow) * K + scol;
  const float* Bptr = B + (bn + srow) * K + scol;

  float4 pa[4], pb[4];
#pragma unroll
  for (int i = 0; i < 4; i++) {
    pa[i] = *(const float4*)(Aptr + i * 4);
    pb[i] = *(const float4*)(Bptr + i * 4);
  }

  for (int k0 = 0; k0 < K; k0 += 32) {
    __syncthreads();
#pragma unroll
    for (int i = 0; i < 4; i++) {
      uint32_t* ad = &As[srow][scol + i * 4];
      ad[0] = f2tf32(pa[i].x); ad[1] = f2tf32(pa[i].y);
      ad[2] = f2tf32(pa[i].z); ad[3] = f2tf32(pa[i].w);
      uint32_t* bd = &Bs[srow][scol + i * 4];
      bd[0] = f2tf32(pb[i].x); bd[1] = f2tf32(pb[i].y);
      bd[2] = f2tf32(pb[i].z); bd[3] = f2tf32(pb[i].w);
    }
    __syncthreads();

    if (k0 + 32 < K) {
#pragma unroll
      for (int i = 0; i < 4; i++) {
        pa[i] = *(const float4*)(Aptr + k0 + 32 + i * 4);
        pb[i] = *(const float4*)(Bptr + k0 + 32 + i * 4);
      }
    }

#pragma unroll
    for (int kk = 0; kk < 4; kk++) {
      uint32_t af[4][4], bf[4][2];
#pragma unroll
      for (int i = 0; i < 4; i++) {
        const int r = wm * 64 + i * 16 + l4;
        af[i][0] = As[r][kk * 8 + lm4];
        af[i][1] = As[r + 8][kk * 8 + lm4];
        af[i][2] = As[r][kk * 8 + lm4 + 4];
        af[i][3] = As[r + 8][kk * 8 + lm4 + 4];
      }
#pragma unroll
      for (int j = 0; j < 4; j++) {
        const int n = wn * 32 + j * 8 + l4;
        bf[j][0] = Bs[n][kk * 8 + lm4];
        bf[j][1] = Bs[n][kk * 8 + lm4 + 4];
      }
#pragma unroll
      for (int i = 0; i < 4; i++)
#pragma unroll
        for (int j = 0; j < 4; j++) mma_tf32(acc[i][j], af[i], bf[j]);
    }
  }

#pragma unroll
  for (int j = 0; j < 4; j++) {
    const int c = bn + wn * 32 + j * 8 + lm4 * 2;
    const float bi0 = bias[c], bi1 = bias[c + 1];
#pragma unroll
    for (int i = 0; i < 4; i++) {
      const int r = bm + wm * 64 + i * 16 + l4;
      float2 o0 = make_float2(acc[i][j][0] + bi0, acc[i][j][1] + bi1);
      float2 o1 = make_float2(acc[i][j][2] + bi0, acc[i][j][3] + bi1);
      *(float2*)(Cout + r * N + c) = o0;
      *(float2*)(Cout + (r + 8) * N + c) = o1;
    }
  }
}

// ---------------------------------------------------------------------------
// Causal flash attention on tf32 tensor cores.
// CTA: 128 q-rows x 1 head, 8 warps, warp = 16 q-rows (softmax warp-local).
// KV tile = 64. Q fragments persist in registers. P round-trips via smem.
// Pitch 68: fragment LDS bank = lane (conflict-free).
// ---------------------------------------------------------------------------
#define APQ 68
#define ATTN_SMEM ((2 * 64 * APQ + 128 * APQ) * sizeof(uint32_t))  // 69,632 B

__global__ __launch_bounds__(256, 2) void flash_attn_tc(
    const float* __restrict__ Q, const float* __restrict__ K,
    const float* __restrict__ V, float* __restrict__ O) {
  extern __shared__ uint32_t smu[];
  uint32_t* Ks = smu;                 // [64][APQ]  Ks[krow][d]
  uint32_t* Vt = Ks + 64 * APQ;       // [64][APQ]  Vt[d][krow]
  uint32_t* Ps = Vt + 64 * APQ;       // [128][APQ] Ps[qrow][kcol] (also Q stage)

  const int qb = gridDim.x - 1 - blockIdx.x;  // heavy q-blocks first
  const int h  = blockIdx.y;
  const int tid = threadIdx.x;
  const int lane = tid & 31;
  const int w = tid >> 5;
  const int l4 = lane >> 2;    // 0..7
  const int lm4 = lane & 3;    // 0..3
  const float scale2 = 0.125f * 1.44269504088896f;  // 1/sqrt(64) * log2(e)

  // ---- stage Q [128][64] (tf32) into Ps, then snapshot warp A-fragments ----
  {
    const int r = tid >> 1;
    const int cb = (tid & 1) * 32;
    const float* src = Q + (qb * 128 + r) * C_MODEL + h * DHEAD + cb;
#pragma unroll
    for (int i = 0; i < 8; i++) {
      float4 v4 = *(const float4*)(src + i * 4);
      uint32_t* d = &Ps[r * APQ + cb + i * 4];
      d[0] = f2tf32(v4.x); d[1] = f2tf32(v4.y);
      d[2] = f2tf32(v4.z); d[3] = f2tf32(v4.w);
    }
  }
  __syncthreads();

  uint32_t qf[8][4];
  {
    const int m0 = w * 16;
#pragma unroll
    for (int kk = 0; kk < 8; kk++) {
      qf[kk][0] = Ps[(m0 + l4) * APQ + kk * 8 + lm4];
      qf[kk][1] = Ps[(m0 + l4 + 8) * APQ + kk * 8 + lm4];
      qf[kk][2] = Ps[(m0 + l4) * APQ + kk * 8 + lm4 + 4];
      qf[kk][3] = Ps[(m0 + l4 + 8) * APQ + kk * 8 + lm4 + 4];
    }
  }

  float m_i[2] = {-1e30f, -1e30f};
  float l_i[2] = {0.f, 0.f};
  float oacc[8][4];
#pragma unroll
  for (int j = 0; j < 8; j++)
#pragma unroll
    for (int c = 0; c < 4; c++) oacc[j][c] = 0.f;

  const int wrow_last = qb * 128 + w * 16 + 15;  // last q row this warp owns
  const int nkt = 2 * qb + 2;

  for (int kt = 0; kt < nkt; kt++) {
    __syncthreads();  // previous iteration's Ks/Vt readers are done
    {
      const int r = tid >> 2;             // 0..63
      const int cb = (tid & 3) * 16;      // 0,16,32,48
      const float* ks = K + (kt * 64 + r) * C_MODEL + h * DHEAD + cb;
      const float* vs = V + (kt * 64 + r) * C_MODEL + h * DHEAD + cb;
#pragma unroll
      for (int i = 0; i < 4; i++) {
        float4 kv = *(const float4*)(ks + i * 4);
        uint32_t* kd = &Ks[r * APQ + cb + i * 4];
        kd[0] = f2tf32(kv.x); kd[1] = f2tf32(kv.y);
        kd[2] = f2tf32(kv.z); kd[3] = f2tf32(kv.w);
        float4 vv = *(const float4*)(vs + i * 4);
        Vt[(cb + i * 4 + 0) * APQ + r] = f2tf32(vv.x);
        Vt[(cb + i * 4 + 1) * APQ + r] = f2tf32(vv.y);
        Vt[(cb + i * 4 + 2) * APQ + r] = f2tf32(vv.z);
        Vt[(cb + i * 4 + 3) * APQ + r] = f2tf32(vv.w);
      }
    }
    __syncthreads();

    if (kt * 64 > wrow_last) continue;  // tile fully above causal diag for warp

    // ---- S = Q K^T : warp computes 16 x 64 ----
    float sc[8][4];
#pragma unroll
    for (int j = 0; j < 8; j++)
#pragma unroll
      for (int c = 0; c < 4; c++) sc[j][c] = 0.f;
#pragma unroll
    for (int kk = 0; kk < 8; kk++) {
#pragma unroll
      for (int j = 0; j < 8; j++) {
        uint32_t bf[2];
        bf[0] = Ks[(j * 8 + l4) * APQ + kk * 8 + lm4];
        bf[1] = Ks[(j * 8 + l4) * APQ + kk * 8 + lm4 + 4];
        mma_tf32(sc[j], qf[kk], bf);
      }
    }

    // ---- scale (log2 domain) + causal mask on diagonal tiles ----
    if (kt >= 2 * qb) {
      const int r0 = qb * 128 + w * 16 + l4;
#pragma unroll
      for (int j = 0; j < 8; j++) {
        const int c0 = kt * 64 + j * 8 + 2 * lm4;
        sc[j][0] = (c0 > r0) ? -1e30f : sc[j][0] * scale2;
        sc[j][1] = (c0 + 1 > r0) ? -1e30f : sc[j][1] * scale2;
        sc[j][2] = (c0 > r0 + 8) ? -1e30f : sc[j][2] * scale2;
        sc[j][3] = (c0 + 1 > r0 + 8) ? -1e30f : sc[j][3] * scale2;
      }
    } else {
#pragma unroll
      for (int j = 0; j < 8; j++)
#pragma unroll
        for (int c = 0; c < 4; c++) sc[j][c] *= scale2;
    }

    // ---- online softmax (two row-halves per lane; 4-lane reductions) ----
#pragma unroll
    for (int rh = 0; rh < 2; rh++) {
      const int cb = rh * 2;
      float rm = sc[0][cb];
#pragma unroll
      for (int j = 0; j < 8; j++)
        rm = fmaxf(rm, fmaxf(sc[j][cb], sc[j][cb + 1]));
      rm = fmaxf(rm, __shfl_xor_sync(0xffffffffu, rm, 1));
      rm = fmaxf(rm, __shfl_xor_sync(0xffffffffu, rm, 2));
      const float mnew = fmaxf(m_i[rh], rm);
      const float alpha = exp2f(m_i[rh] - mnew);
      float rs = 0.f;
#pragma unroll
      for (int j = 0; j < 8; j++) {
        const float p0 = exp2f(sc[j][cb] - mnew);
        const float p1 = exp2f(sc[j][cb + 1] - mnew);
        sc[j][cb] = p0; sc[j][cb + 1] = p1;
        rs += p0 + p1;
      }
      rs += __shfl_xor_sync(0xffffffffu, rs, 1);
      rs += __shfl_xor_sync(0xffffffffu, rs, 2);
      l_i[rh] = l_i[rh] * alpha + rs;
      m_i[rh] = mnew;
#pragma unroll
      for (int j = 0; j < 8; j++) {
        oacc[j][cb] *= alpha;
        oacc[j][cb + 1] *= alpha;
      }
      // store P row (tf32) into warp-private Ps rows
      const int pr = (w * 16 + l4 + rh * 8) * APQ + 2 * lm4;
#pragma unroll
      for (int j = 0; j < 8; j++) {
        uint2 pp = make_uint2(f2tf32(sc[j][cb]), f2tf32(sc[j][cb + 1]));
        *(uint2*)&Ps[pr + j * 8] = pp;
      }
    }
    __syncwarp();

    // ---- O += P V : A = Ps (warp rows), B = Vt ----
#pragma unroll
    for (int kk = 0; kk < 8; kk++) {
      uint32_t af[4];
      af[0] = Ps[(w * 16 + l4) * APQ + kk * 8 + lm4];
      af[1] = Ps[(w * 16 + l4 + 8) * APQ + kk * 8 + lm4];
      af[2] = Ps[(w * 16 + l4) * APQ + kk * 8 + lm4 + 4];
      af[3] = Ps[(w * 16 + l4 + 8) * APQ + kk * 8 + lm4 + 4];
#pragma unroll
      for (int j = 0; j < 8; j++) {
        uint32_t bf[2];
        bf[0] = Vt[(j * 8 + l4) * APQ + kk * 8 + lm4];
        bf[1] = Vt[(j * 8 + l4) * APQ + kk * 8 + lm4 + 4];
        mma_tf32(oacc[j], af, bf);
      }
    }
    __syncwarp();  // PV reads of Ps done before next iteration's P writes
  }

  // ---- epilogue: normalize, store [T, C] head-interleaved ----
#pragma unroll
  for (int rh = 0; rh < 2; rh++) {
    const float inv = 1.f / l_i[rh];
    const int r = qb * 128 + w * 16 + l4 + rh * 8;
    float* dst = O + r * C_MODEL + h * DHEAD + 2 * lm4;
#pragma unroll
    for (int j = 0; j < 8; j++) {
      float2 o = make_float2(oacc[j][rh * 2] * inv, oacc[j][rh * 2 + 1] * inv);
      *(float2*)(dst + j * 8) = o;
    }
  }
}

// ---------------------------------------------------------------------------
extern "C" void kernel_launch(void* const* d_in, const int* in_sizes, int n_in,
                              void* d_out, int out_size) {
  const float* x  = (const float*)d_in[0];
  const float* Wq = (const float*)d_in[1];
  const float* bq = (const float*)d_in[2];
  const float* Wk = (const float*)d_in[3];
  const float* bk = (const float*)d_in[4];
  const float* Wv = (const float*)d_in[5];
  const float* bv = (const float*)d_in[6];
  const float* Wo = (const float*)d_in[7];
  const float* bo = (const float*)d_in[8];
  float* out = (float*)d_out;

  float *qp, *kp, *vp, *ap;
  cudaGetSymbolAddress((void**)&qp, g_q);
  cudaGetSymbolAddress((void**)&kp, g_k);
  cudaGetSymbolAddress((void**)&vp, g_v);
  cudaGetSymbolAddress((void**)&ap, g_attn);

  cudaFuncSetAttribute(flash_attn_tc, cudaFuncAttributeMaxDynamicSharedMemorySize,
                       (int)ATTN_SMEM);

  dim3 gb(C_MODEL / 128, T_SEQ / 128);  // (8, 32)
  gemm_bias_tc<<<gb, 256>>>(x, Wq, bq, qp, T_SEQ, C_MODEL, C_MODEL);
  gemm_bias_tc<<<gb, 256>>>(x, Wk, bk, kp, T_SEQ, C_MODEL, C_MODEL);
  gemm_bias_tc<<<gb, 256>>>(x, Wv, bv, vp, T_SEQ, C_MODEL, C_MODEL);

  dim3 ga(T_SEQ / 128, NHEADS);         // (32, 16)
  flash_attn_tc<<<ga, 256, ATTN_SMEM>>>(qp, kp, vp, ap);

  gemm_bias_tc<<<gb, 256>>>(ap, Wo, bo, out, T_SEQ, C_MODEL, C_MODEL);
}

// round 9
// speedup vs baseline: 1.9017x; 1.0373x over previous
#include <cuda_runtime.h>
#include <math.h>
#include <stdint.h>

#define T_SEQ 4096
#define C_MODEL 1024
#define NHEADS 16
#define DHEAD 64

// Scratch (allocation-free rule: __device__ globals)
__device__ float g_q[T_SEQ * C_MODEL];
__device__ float g_k[T_SEQ * C_MODEL];
__device__ float g_v[T_SEQ * C_MODEL];
__device__ float g_attn[T_SEQ * C_MODEL];

__device__ __forceinline__ uint32_t f2tf32(float x) {
  uint32_t r;
  asm("cvt.rna.tf32.f32 %0, %1;" : "=r"(r) : "f"(x));
  return r;
}

__device__ __forceinline__ void mma_tf32(float* d, const uint32_t* a,
                                         const uint32_t* b) {
  asm volatile(
      "mma.sync.aligned.m16n8k8.row.col.f32.tf32.tf32.f32 "
      "{%0,%1,%2,%3}, {%4,%5,%6,%7}, {%8,%9}, {%0,%1,%2,%3};\n"
      : "+f"(d[0]), "+f"(d[1]), "+f"(d[2]), "+f"(d[3])
      : "r"(a[0]), "r"(a[1]), "r"(a[2]), "r"(a[3]), "r"(b[0]), "r"(b[1]));
}

__device__ __forceinline__ void cp16(uint32_t smem_addr, const void* gptr) {
  asm volatile("cp.async.cg.shared.global [%0], [%1], 16;" ::"r"(smem_addr),
               "l"(gptr));
}
#define CP_COMMIT() asm volatile("cp.async.commit_group;")
#define CP_WAIT1() asm volatile("cp.async.wait_group 1;")

// ---------------------------------------------------------------------------
// C[M,N] = A[M,K] @ B[N,K]^T + bias[N]   (tf32 tensor cores)
// ROUND: round outputs to tf32 bit patterns (for q/k/v consumed by attention).
// ---------------------------------------------------------------------------
#define TPITCH 36

template <bool ROUND>
__global__ __launch_bounds__(256) void gemm_bias_tc(
    const float* __restrict__ A, const float* __restrict__ B,
    const float* __restrict__ bias, float* __restrict__ Cout,
    int M, int N, int K) {
  __shared__ uint32_t As[128][TPITCH];
  __shared__ uint32_t Bs[128][TPITCH];

  const int tid = threadIdx.x;
  const int lane = tid & 31;
  const int wid = tid >> 5;
  const int wm = wid >> 2;
  const int wn = wid & 3;
  const int l4 = lane >> 2;
  const int lm4 = lane & 3;
  const int bm = blockIdx.y * 128;
  const int bn = blockIdx.x * 128;

  const int srow = tid >> 1;
  const int scol = (tid & 1) * 16;

  float acc[4][4][4];
#pragma unroll
  for (int i = 0; i < 4; i++)
#pragma unroll
    for (int j = 0; j < 4; j++)
#pragma unroll
      for (int c = 0; c < 4; c++) acc[i][j][c] = 0.f;

  const float* Aptr = A + (bm + srow) * K + scol;
  const float* Bptr = B + (bn + srow) * K + scol;

  float4 pa[4], pb[4];
#pragma unroll
  for (int i = 0; i < 4; i++) {
    pa[i] = *(const float4*)(Aptr + i * 4);
    pb[i] = *(const float4*)(Bptr + i * 4);
  }

  for (int k0 = 0; k0 < K; k0 += 32) {
    __syncthreads();
#pragma unroll
    for (int i = 0; i < 4; i++) {
      uint32_t* ad = &As[srow][scol + i * 4];
      ad[0] = f2tf32(pa[i].x); ad[1] = f2tf32(pa[i].y);
      ad[2] = f2tf32(pa[i].z); ad[3] = f2tf32(pa[i].w);
      uint32_t* bd = &Bs[srow][scol + i * 4];
      bd[0] = f2tf32(pb[i].x); bd[1] = f2tf32(pb[i].y);
      bd[2] = f2tf32(pb[i].z); bd[3] = f2tf32(pb[i].w);
    }
    __syncthreads();

    if (k0 + 32 < K) {
#pragma unroll
      for (int i = 0; i < 4; i++) {
        pa[i] = *(const float4*)(Aptr + k0 + 32 + i * 4);
        pb[i] = *(const float4*)(Bptr + k0 + 32 + i * 4);
      }
    }

#pragma unroll
    for (int kk = 0; kk < 4; kk++) {
      uint32_t af[4][4], bf[4][2];
#pragma unroll
      for (int i = 0; i < 4; i++) {
        const int r = wm * 64 + i * 16 + l4;
        af[i][0] = As[r][kk * 8 + lm4];
        af[i][1] = As[r + 8][kk * 8 + lm4];
        af[i][2] = As[r][kk * 8 + lm4 + 4];
        af[i][3] = As[r + 8][kk * 8 + lm4 + 4];
      }
#pragma unroll
      for (int j = 0; j < 4; j++) {
        const int n = wn * 32 + j * 8 + l4;
        bf[j][0] = Bs[n][kk * 8 + lm4];
        bf[j][1] = Bs[n][kk * 8 + lm4 + 4];
      }
#pragma unroll
      for (int i = 0; i < 4; i++)
#pragma unroll
        for (int j = 0; j < 4; j++) mma_tf32(acc[i][j], af[i], bf[j]);
    }
  }

#pragma unroll
  for (int j = 0; j < 4; j++) {
    const int c = bn + wn * 32 + j * 8 + lm4 * 2;
    const float bi0 = bias[c], bi1 = bias[c + 1];
#pragma unroll
    for (int i = 0; i < 4; i++) {
      const int r = bm + wm * 64 + i * 16 + l4;
      float v00 = acc[i][j][0] + bi0, v01 = acc[i][j][1] + bi1;
      float v10 = acc[i][j][2] + bi0, v11 = acc[i][j][3] + bi1;
      if (ROUND) {
        v00 = __uint_as_float(f2tf32(v00));
        v01 = __uint_as_float(f2tf32(v01));
        v10 = __uint_as_float(f2tf32(v10));
        v11 = __uint_as_float(f2tf32(v11));
      }
      *(float2*)(Cout + r * N + c) = make_float2(v00, v01);
      *(float2*)(Cout + (r + 8) * N + c) = make_float2(v10, v11);
    }
  }
}

// ---------------------------------------------------------------------------
// Causal flash attention on tf32 tensor cores, cp.async double-buffered K/V.
// CTA: 128 q-rows x 1 head, 8 warps (warp = 16 q-rows, softmax warp-local).
// K/V arrive pre-rounded to tf32 bit patterns (by the projection GEMMs), so
// they are copied gmem->smem raw. K: [krow][d] pitch 68 (frag bank = lane);
// V: [krow][d] pitch 76 (frag bank = perfect permutation). P via smem pitch 68.
// ---------------------------------------------------------------------------
#define KS_W 68
#define VS_W 76
#define SM_KS 0
#define SM_VS (2 * 64 * KS_W)
#define SM_PS (SM_VS + 2 * 64 * VS_W)
#define ATTN_WORDS (SM_PS + 128 * KS_W)
#define ATTN_SMEM (ATTN_WORDS * sizeof(uint32_t))  // 108,544 B

__global__ __launch_bounds__(256, 2) void flash_attn_tc(
    const float* __restrict__ Q, const float* __restrict__ K,
    const float* __restrict__ V, float* __restrict__ O) {
  extern __shared__ uint32_t smu[];
  const uint32_t sbase = (uint32_t)__cvta_generic_to_shared(smu);
  uint32_t* Ps = smu + SM_PS;  // [128][KS_W]

  const int qb = gridDim.x - 1 - blockIdx.x;  // heavy q-blocks first
  const int h  = blockIdx.y;
  const int tid = threadIdx.x;
  const int lane = tid & 31;
  const int w = tid >> 5;
  const int l4 = lane >> 2;    // 0..7
  const int lm4 = lane & 3;    // 0..3
  const float scale2 = 0.125f * 1.44269504088896f;  // 1/sqrt(64) * log2(e)
  const int nkt = 2 * qb + 2;

  // issue cp.async for tile 0 (overlaps with Q staging below)
  {
#pragma unroll
    for (int i = 0; i < 4; i++) {
      const int c = tid + i * 256;           // chunk id 0..1023
      const int row = c >> 4, col4 = (c & 15) << 2;
      cp16(sbase + (SM_KS + row * KS_W + col4) * 4,
           K + (0 * 64 + row) * C_MODEL + h * DHEAD + col4);
      cp16(sbase + (SM_VS + row * VS_W + col4) * 4,
           V + (0 * 64 + row) * C_MODEL + h * DHEAD + col4);
    }
    CP_COMMIT();
  }

  // ---- stage Q [128][64] (already tf32-rounded) into Ps ----
  {
    const int r = tid >> 1;
    const int cb = (tid & 1) * 32;
    const uint32_t* src =
        (const uint32_t*)(Q + (qb * 128 + r) * C_MODEL + h * DHEAD + cb);
#pragma unroll
    for (int i = 0; i < 8; i++) {
      uint4 v4 = *(const uint4*)(src + i * 4);
      uint32_t* d = &Ps[r * KS_W + cb + i * 4];
      d[0] = v4.x; d[1] = v4.y; d[2] = v4.z; d[3] = v4.w;
    }
  }
  __syncthreads();

  uint32_t qf[8][4];
  {
    const int m0 = w * 16;
#pragma unroll
    for (int kk = 0; kk < 8; kk++) {
      qf[kk][0] = Ps[(m0 + l4) * KS_W + kk * 8 + lm4];
      qf[kk][1] = Ps[(m0 + l4 + 8) * KS_W + kk * 8 + lm4];
      qf[kk][2] = Ps[(m0 + l4) * KS_W + kk * 8 + lm4 + 4];
      qf[kk][3] = Ps[(m0 + l4 + 8) * KS_W + kk * 8 + lm4 + 4];
    }
  }

  float m_i[2] = {-1e30f, -1e30f};
  float l_i[2] = {0.f, 0.f};
  float oacc[8][4];
#pragma unroll
  for (int j = 0; j < 8; j++)
#pragma unroll
    for (int c = 0; c < 4; c++) oacc[j][c] = 0.f;

  const int wrow_last = qb * 128 + w * 16 + 15;

  for (int kt = 0; kt < nkt; kt++) {
    // issue next tile's loads into the other buffer
    if (kt + 1 < nkt) {
      const int nb = (kt + 1) & 1;
#pragma unroll
      for (int i = 0; i < 4; i++) {
        const int c = tid + i * 256;
        const int row = c >> 4, col4 = (c & 15) << 2;
        cp16(sbase + (SM_KS + nb * 64 * KS_W + row * KS_W + col4) * 4,
             K + ((kt + 1) * 64 + row) * C_MODEL + h * DHEAD + col4);
        cp16(sbase + (SM_VS + nb * 64 * VS_W + row * VS_W + col4) * 4,
             V + ((kt + 1) * 64 + row) * C_MODEL + h * DHEAD + col4);
      }
    }
    CP_COMMIT();
    CP_WAIT1();       // tile kt resident
    __syncthreads();

    if (kt * 64 <= wrow_last) {  // tile not fully above causal diag for warp
      const uint32_t* Ks = smu + SM_KS + (kt & 1) * 64 * KS_W;
      const uint32_t* Vs = smu + SM_VS + (kt & 1) * 64 * VS_W;

      // ---- S = Q K^T : warp computes 16 x 64 ----
      float sc[8][4];
#pragma unroll
      for (int j = 0; j < 8; j++)
#pragma unroll
        for (int c = 0; c < 4; c++) sc[j][c] = 0.f;
#pragma unroll
      for (int kk = 0; kk < 8; kk++) {
#pragma unroll
        for (int j = 0; j < 8; j++) {
          uint32_t bf[2];
          bf[0] = Ks[(j * 8 + l4) * KS_W + kk * 8 + lm4];
          bf[1] = Ks[(j * 8 + l4) * KS_W + kk * 8 + lm4 + 4];
          mma_tf32(sc[j], qf[kk], bf);
        }
      }

      // ---- scale (log2 domain) + causal mask on diagonal tiles ----
      if (kt >= 2 * qb) {
        const int r0 = qb * 128 + w * 16 + l4;
#pragma unroll
        for (int j = 0; j < 8; j++) {
          const int c0 = kt * 64 + j * 8 + 2 * lm4;
          sc[j][0] = (c0 > r0) ? -1e30f : sc[j][0] * scale2;
          sc[j][1] = (c0 + 1 > r0) ? -1e30f : sc[j][1] * scale2;
          sc[j][2] = (c0 > r0 + 8) ? -1e30f : sc[j][2] * scale2;
          sc[j][3] = (c0 + 1 > r0 + 8) ? -1e30f : sc[j][3] * scale2;
        }
      } else {
#pragma unroll
        for (int j = 0; j < 8; j++)
#pragma unroll
          for (int c = 0; c < 4; c++) sc[j][c] *= scale2;
      }

      // ---- online softmax ----
#pragma unroll
      for (int rh = 0; rh < 2; rh++) {
        const int cb = rh * 2;
        float rm = sc[0][cb];
#pragma unroll
        for (int j = 0; j < 8; j++)
          rm = fmaxf(rm, fmaxf(sc[j][cb], sc[j][cb + 1]));
        rm = fmaxf(rm, __shfl_xor_sync(0xffffffffu, rm, 1));
        rm = fmaxf(rm, __shfl_xor_sync(0xffffffffu, rm, 2));
        const float mnew = fmaxf(m_i[rh], rm);
        const float alpha = exp2f(m_i[rh] - mnew);
        float rs = 0.f;
#pragma unroll
        for (int j = 0; j < 8; j++) {
          const float p0 = exp2f(sc[j][cb] - mnew);
          const float p1 = exp2f(sc[j][cb + 1] - mnew);
          sc[j][cb] = p0; sc[j][cb + 1] = p1;
          rs += p0 + p1;
        }
        rs += __shfl_xor_sync(0xffffffffu, rs, 1);
        rs += __shfl_xor_sync(0xffffffffu, rs, 2);
        l_i[rh] = l_i[rh] * alpha + rs;
        m_i[rh] = mnew;
#pragma unroll
        for (int j = 0; j < 8; j++) {
          oacc[j][cb] *= alpha;
          oacc[j][cb + 1] *= alpha;
        }
        const int pr = (w * 16 + l4 + rh * 8) * KS_W + 2 * lm4;
#pragma unroll
        for (int j = 0; j < 8; j++) {
          uint2 pp = make_uint2(f2tf32(sc[j][cb]), f2tf32(sc[j][cb + 1]));
          *(uint2*)&Ps[pr + j * 8] = pp;
        }
      }
      __syncwarp();

      // ---- O += P V ----
#pragma unroll
      for (int kk = 0; kk < 8; kk++) {
        uint32_t af[4];
        af[0] = Ps[(w * 16 + l4) * KS_W + kk * 8 + lm4];
        af[1] = Ps[(w * 16 + l4 + 8) * KS_W + kk * 8 + lm4];
        af[2] = Ps[(w * 16 + l4) * KS_W + kk * 8 + lm4 + 4];
        af[3] = Ps[(w * 16 + l4 + 8) * KS_W + kk * 8 + lm4 + 4];
#pragma unroll
        for (int j = 0; j < 8; j++) {
          uint32_t bf[2];
          bf[0] = Vs[(kk * 8 + lm4) * VS_W + j * 8 + l4];
          bf[1] = Vs[(kk * 8 + lm4 + 4) * VS_W + j * 8 + l4];
          mma_tf32(oacc[j], af, bf);
        }
      }
      __syncwarp();
    }
    __syncthreads();  // all warps done with buf (kt&1) before reuse
  }

  // ---- epilogue: normalize, store [T, C] head-interleaved ----
#pragma unroll
  for (int rh = 0; rh < 2; rh++) {
    const float inv = 1.f / l_i[rh];
    const int r = qb * 128 + w * 16 + l4 + rh * 8;
    float* dst = O + r * C_MODEL + h * DHEAD + 2 * lm4;
#pragma unroll
    for (int j = 0; j < 8; j++) {
      float2 o = make_float2(oacc[j][rh * 2] * inv, oacc[j][rh * 2 + 1] * inv);
      *(float2*)(dst + j * 8) = o;
    }
  }
}

// ---------------------------------------------------------------------------
extern "C" void kernel_launch(void* const* d_in, const int* in_sizes, int n_in,
                              void* d_out, int out_size) {
  const float* x  = (const float*)d_in[0];
  const float* Wq = (const float*)d_in[1];
  const float* bq = (const float*)d_in[2];
  const float* Wk = (const float*)d_in[3];
  const float* bk = (const float*)d_in[4];
  const float* Wv = (const float*)d_in[5];
  const float* bv = (const float*)d_in[6];
  const float* Wo = (const float*)d_in[7];
  const float* bo = (const float*)d_in[8];
  float* out = (float*)d_out;

  float *qp, *kp, *vp, *ap;
  cudaGetSymbolAddress((void**)&qp, g_q);
  cudaGetSymbolAddress((void**)&kp, g_k);
  cudaGetSymbolAddress((void**)&vp, g_v);
  cudaGetSymbolAddress((void**)&ap, g_attn);

  cudaFuncSetAttribute(flash_attn_tc, cudaFuncAttributeMaxDynamicSharedMemorySize,
                       (int)ATTN_SMEM);

  dim3 gb(C_MODEL / 128, T_SEQ / 128);  // (8, 32)
  gemm_bias_tc<true><<<gb, 256>>>(x, Wq, bq, qp, T_SEQ, C_MODEL, C_MODEL);
  gemm_bias_tc<true><<<gb, 256>>>(x, Wk, bk, kp, T_SEQ, C_MODEL, C_MODEL);
  gemm_bias_tc<true><<<gb, 256>>>(x, Wv, bv, vp, T_SEQ, C_MODEL, C_MODEL);

  dim3 ga(T_SEQ / 128, NHEADS);         // (32, 16)
  flash_attn_tc<<<ga, 256, ATTN_SMEM>>>(qp, kp, vp, ap);

  gemm_bias_tc<false><<<gb, 256>>>(ap, Wo, bo, out, T_SEQ, C_MODEL, C_MODEL);
}

// round 10
// speedup vs baseline: 1.9174x; 1.0082x over previous
#include <cuda_runtime.h>
#include <math.h>
#include <stdint.h>

#define T_SEQ 4096
#define C_MODEL 1024
#define NHEADS 16
#define DHEAD 64

// Scratch (allocation-free rule: __device__ globals)
__device__ float g_q[T_SEQ * C_MODEL];
__device__ float g_k[T_SEQ * C_MODEL];
__device__ float g_v[T_SEQ * C_MODEL];
__device__ float g_attn[T_SEQ * C_MODEL];

__device__ __forceinline__ uint32_t f2tf32(float x) {
  uint32_t r;
  asm("cvt.rna.tf32.f32 %0, %1;" : "=r"(r) : "f"(x));
  return r;
}

__device__ __forceinline__ void mma_tf32(float* d, const uint32_t* a,
                                         const uint32_t* b) {
  asm volatile(
      "mma.sync.aligned.m16n8k8.row.col.f32.tf32.tf32.f32 "
      "{%0,%1,%2,%3}, {%4,%5,%6,%7}, {%8,%9}, {%0,%1,%2,%3};\n"
      : "+f"(d[0]), "+f"(d[1]), "+f"(d[2]), "+f"(d[3])
      : "r"(a[0]), "r"(a[1]), "r"(a[2]), "r"(a[3]), "r"(b[0]), "r"(b[1]));
}

__device__ __forceinline__ void cp16(uint32_t smem_addr, const void* gptr) {
  asm volatile("cp.async.cg.shared.global [%0], [%1], 16;" ::"r"(smem_addr),
               "l"(gptr));
}
#define CP_COMMIT() asm volatile("cp.async.commit_group;")
#define CP_WAIT1() asm volatile("cp.async.wait_group 1;")

// ---------------------------------------------------------------------------
// Shared tf32 GEMM body: C[M,N] = A[M,K] @ B[N,K]^T + bias[N]
// CTA tile 128x128, BK=32, 8 warps (2m x 4n), warp tile 64x32.
// ---------------------------------------------------------------------------
#define TPITCH 36

template <bool ROUND>
__device__ __forceinline__ void gemm_body(
    const float* __restrict__ A, const float* __restrict__ B,
    const float* __restrict__ bias, float* __restrict__ Cout,
    int M, int N, int K, int bm, int bn) {
  __shared__ uint32_t As[128][TPITCH];
  __shared__ uint32_t Bs[128][TPITCH];

  const int tid = threadIdx.x;
  const int lane = tid & 31;
  const int wid = tid >> 5;
  const int wm = wid >> 2;
  const int wn = wid & 3;
  const int l4 = lane >> 2;
  const int lm4 = lane & 3;

  const int srow = tid >> 1;
  const int scol = (tid & 1) * 16;

  float acc[4][4][4];
#pragma unroll
  for (int i = 0; i < 4; i++)
#pragma unroll
    for (int j = 0; j < 4; j++)
#pragma unroll
      for (int c = 0; c < 4; c++) acc[i][j][c] = 0.f;

  const float* Aptr = A + (bm + srow) * K + scol;
  const float* Bptr = B + (bn + srow) * K + scol;

  float4 pa[4], pb[4];
#pragma unroll
  for (int i = 0; i < 4; i++) {
    pa[i] = *(const float4*)(Aptr + i * 4);
    pb[i] = *(const float4*)(Bptr + i * 4);
  }

  for (int k0 = 0; k0 < K; k0 += 32) {
    __syncthreads();
#pragma unroll
    for (int i = 0; i < 4; i++) {
      uint32_t* ad = &As[srow][scol + i * 4];
      ad[0] = f2tf32(pa[i].x); ad[1] = f2tf32(pa[i].y);
      ad[2] = f2tf32(pa[i].z); ad[3] = f2tf32(pa[i].w);
      uint32_t* bd = &Bs[srow][scol + i * 4];
      bd[0] = f2tf32(pb[i].x); bd[1] = f2tf32(pb[i].y);
      bd[2] = f2tf32(pb[i].z); bd[3] = f2tf32(pb[i].w);
    }
    __syncthreads();

    if (k0 + 32 < K) {
#pragma unroll
      for (int i = 0; i < 4; i++) {
        pa[i] = *(const float4*)(Aptr + k0 + 32 + i * 4);
        pb[i] = *(const float4*)(Bptr + k0 + 32 + i * 4);
      }
    }

#pragma unroll
    for (int kk = 0; kk < 4; kk++) {
      uint32_t af[4][4], bf[4][2];
#pragma unroll
      for (int i = 0; i < 4; i++) {
        const int r = wm * 64 + i * 16 + l4;
        af[i][0] = As[r][kk * 8 + lm4];
        af[i][1] = As[r + 8][kk * 8 + lm4];
        af[i][2] = As[r][kk * 8 + lm4 + 4];
        af[i][3] = As[r + 8][kk * 8 + lm4 + 4];
      }
#pragma unroll
      for (int j = 0; j < 4; j++) {
        const int n = wn * 32 + j * 8 + l4;
        bf[j][0] = Bs[n][kk * 8 + lm4];
        bf[j][1] = Bs[n][kk * 8 + lm4 + 4];
      }
#pragma unroll
      for (int i = 0; i < 4; i++)
#pragma unroll
        for (int j = 0; j < 4; j++) mma_tf32(acc[i][j], af[i], bf[j]);
    }
  }

#pragma unroll
  for (int j = 0; j < 4; j++) {
    const int c = bn + wn * 32 + j * 8 + lm4 * 2;
    const float bi0 = bias[c], bi1 = bias[c + 1];
#pragma unroll
    for (int i = 0; i < 4; i++) {
      const int r = bm + wm * 64 + i * 16 + l4;
      float v00 = acc[i][j][0] + bi0, v01 = acc[i][j][1] + bi1;
      float v10 = acc[i][j][2] + bi0, v11 = acc[i][j][3] + bi1;
      if (ROUND) {
        v00 = __uint_as_float(f2tf32(v00));
        v01 = __uint_as_float(f2tf32(v01));
        v10 = __uint_as_float(f2tf32(v10));
        v11 = __uint_as_float(f2tf32(v11));
      }
      *(float2*)(Cout + r * N + c) = make_float2(v00, v01);
      *(float2*)(Cout + (r + 8) * N + c) = make_float2(v10, v11);
    }
  }
}

// Fused Q/K/V projection: one launch, blockIdx.z selects weight/bias/dst.
// All outputs tf32-rounded (consumed raw by attention).
__global__ __launch_bounds__(256) void gemm_qkv(
    const float* __restrict__ x,
    const float* __restrict__ Wq, const float* __restrict__ bq,
    float* __restrict__ q,
    const float* __restrict__ Wk, const float* __restrict__ bk,
    float* __restrict__ k,
    const float* __restrict__ Wv, const float* __restrict__ bv,
    float* __restrict__ v) {
  const float* B;
  const float* bias;
  float* out;
  if (blockIdx.z == 0) { B = Wq; bias = bq; out = q; }
  else if (blockIdx.z == 1) { B = Wk; bias = bk; out = k; }
  else { B = Wv; bias = bv; out = v; }
  gemm_body<true>(x, B, bias, out, T_SEQ, C_MODEL, C_MODEL,
                  blockIdx.y * 128, blockIdx.x * 128);
}

// Output projection (no rounding).
__global__ __launch_bounds__(256) void gemm_out(
    const float* __restrict__ A, const float* __restrict__ B,
    const float* __restrict__ bias, float* __restrict__ Cout) {
  gemm_body<false>(A, B, bias, Cout, T_SEQ, C_MODEL, C_MODEL,
                   blockIdx.y * 128, blockIdx.x * 128);
}

// ---------------------------------------------------------------------------
// Causal flash attention on tf32 tensor cores, cp.async double-buffered K/V.
// (Unchanged from R9 — attn changes deferred to the structural round.)
// ---------------------------------------------------------------------------
#define KS_W 68
#define VS_W 76
#define SM_KS 0
#define SM_VS (2 * 64 * KS_W)
#define SM_PS (SM_VS + 2 * 64 * VS_W)
#define ATTN_WORDS (SM_PS + 128 * KS_W)
#define ATTN_SMEM (ATTN_WORDS * sizeof(uint32_t))  // 108,544 B

__global__ __launch_bounds__(256, 2) void flash_attn_tc(
    const float* __restrict__ Q, const float* __restrict__ K,
    const float* __restrict__ V, float* __restrict__ O) {
  extern __shared__ uint32_t smu[];
  const uint32_t sbase = (uint32_t)__cvta_generic_to_shared(smu);
  uint32_t* Ps = smu + SM_PS;  // [128][KS_W]

  const int qb = gridDim.x - 1 - blockIdx.x;  // heavy q-blocks first
  const int h  = blockIdx.y;
  const int tid = threadIdx.x;
  const int lane = tid & 31;
  const int w = tid >> 5;
  const int l4 = lane >> 2;
  const int lm4 = lane & 3;
  const float scale2 = 0.125f * 1.44269504088896f;
  const int nkt = 2 * qb + 2;

  // issue cp.async for tile 0
  {
#pragma unroll
    for (int i = 0; i < 4; i++) {
      const int c = tid + i * 256;
      const int row = c >> 4, col4 = (c & 15) << 2;
      cp16(sbase + (SM_KS + row * KS_W + col4) * 4,
           K + (0 * 64 + row) * C_MODEL + h * DHEAD + col4);
      cp16(sbase + (SM_VS + row * VS_W + col4) * 4,
           V + (0 * 64 + row) * C_MODEL + h * DHEAD + col4);
    }
    CP_COMMIT();
  }

  // stage Q [128][64] (already tf32-rounded) into Ps
  {
    const int r = tid >> 1;
    const int cb = (tid & 1) * 32;
    const uint32_t* src =
        (const uint32_t*)(Q + (qb * 128 + r) * C_MODEL + h * DHEAD + cb);
#pragma unroll
    for (int i = 0; i < 8; i++) {
      uint4 v4 = *(const uint4*)(src + i * 4);
      uint32_t* d = &Ps[r * KS_W + cb + i * 4];
      d[0] = v4.x; d[1] = v4.y; d[2] = v4.z; d[3] = v4.w;
    }
  }
  __syncthreads();

  uint32_t qf[8][4];
  {
    const int m0 = w * 16;
#pragma unroll
    for (int kk = 0; kk < 8; kk++) {
      qf[kk][0] = Ps[(m0 + l4) * KS_W + kk * 8 + lm4];
      qf[kk][1] = Ps[(m0 + l4 + 8) * KS_W + kk * 8 + lm4];
      qf[kk][2] = Ps[(m0 + l4) * KS_W + kk * 8 + lm4 + 4];
      qf[kk][3] = Ps[(m0 + l4 + 8) * KS_W + kk * 8 + lm4 + 4];
    }
  }

  float m_i[2] = {-1e30f, -1e30f};
  float l_i[2] = {0.f, 0.f};
  float oacc[8][4];
#pragma unroll
  for (int j = 0; j < 8; j++)
#pragma unroll
    for (int c = 0; c < 4; c++) oacc[j][c] = 0.f;

  const int wrow_last = qb * 128 + w * 16 + 15;

  for (int kt = 0; kt < nkt; kt++) {
    if (kt + 1 < nkt) {
      const int nb = (kt + 1) & 1;
#pragma unroll
      for (int i = 0; i < 4; i++) {
        const int c = tid + i * 256;
        const int row = c >> 4, col4 = (c & 15) << 2;
        cp16(sbase + (SM_KS + nb * 64 * KS_W + row * KS_W + col4) * 4,
             K + ((kt + 1) * 64 + row) * C_MODEL + h * DHEAD + col4);
        cp16(sbase + (SM_VS + nb * 64 * VS_W + row * VS_W + col4) * 4,
             V + ((kt + 1) * 64 + row) * C_MODEL + h * DHEAD + col4);
      }
    }
    CP_COMMIT();
    CP_WAIT1();
    __syncthreads();

    if (kt * 64 <= wrow_last) {
      const uint32_t* Ks = smu + SM_KS + (kt & 1) * 64 * KS_W;
      const uint32_t* Vs = smu + SM_VS + (kt & 1) * 64 * VS_W;

      float sc[8][4];
#pragma unroll
      for (int j = 0; j < 8; j++)
#pragma unroll
        for (int c = 0; c < 4; c++) sc[j][c] = 0.f;
#pragma unroll
      for (int kk = 0; kk < 8; kk++) {
#pragma unroll
        for (int j = 0; j < 8; j++) {
          uint32_t bf[2];
          bf[0] = Ks[(j * 8 + l4) * KS_W + kk * 8 + lm4];
          bf[1] = Ks[(j * 8 + l4) * KS_W + kk * 8 + lm4 + 4];
          mma_tf32(sc[j], qf[kk], bf);
        }
      }

      if (kt >= 2 * qb) {
        const int r0 = qb * 128 + w * 16 + l4;
#pragma unroll
        for (int j = 0; j < 8; j++) {
          const int c0 = kt * 64 + j * 8 + 2 * lm4;
          sc[j][0] = (c0 > r0) ? -1e30f : sc[j][0] * scale2;
          sc[j][1] = (c0 + 1 > r0) ? -1e30f : sc[j][1] * scale2;
          sc[j][2] = (c0 > r0 + 8) ? -1e30f : sc[j][2] * scale2;
          sc[j][3] = (c0 + 1 > r0 + 8) ? -1e30f : sc[j][3] * scale2;
        }
      } else {
#pragma unroll
        for (int j = 0; j < 8; j++)
#pragma unroll
          for (int c = 0; c < 4; c++) sc[j][c] *= scale2;
      }

#pragma unroll
      for (int rh = 0; rh < 2; rh++) {
        const int cb = rh * 2;
        float rm = sc[0][cb];
#pragma unroll
        for (int j = 0; j < 8; j++)
          rm = fmaxf(rm, fmaxf(sc[j][cb], sc[j][cb + 1]));
        rm = fmaxf(rm, __shfl_xor_sync(0xffffffffu, rm, 1));
        rm = fmaxf(rm, __shfl_xor_sync(0xffffffffu, rm, 2));
        const float mnew = fmaxf(m_i[rh], rm);
        const float alpha = exp2f(m_i[rh] - mnew);
        float rs = 0.f;
#pragma unroll
        for (int j = 0; j < 8; j++) {
          const float p0 = exp2f(sc[j][cb] - mnew);
          const float p1 = exp2f(sc[j][cb + 1] - mnew);
          sc[j][cb] = p0; sc[j][cb + 1] = p1;
          rs += p0 + p1;
        }
        rs += __shfl_xor_sync(0xffffffffu, rs, 1);
        rs += __shfl_xor_sync(0xffffffffu, rs, 2);
        l_i[rh] = l_i[rh] * alpha + rs;
        m_i[rh] = mnew;
#pragma unroll
        for (int j = 0; j < 8; j++) {
          oacc[j][cb] *= alpha;
          oacc[j][cb + 1] *= alpha;
        }
        const int pr = (w * 16 + l4 + rh * 8) * KS_W + 2 * lm4;
#pragma unroll
        for (int j = 0; j < 8; j++) {
          uint2 pp = make_uint2(f2tf32(sc[j][cb]), f2tf32(sc[j][cb + 1]));
          *(uint2*)&Ps[pr + j * 8] = pp;
        }
      }
      __syncwarp();

#pragma unroll
      for (int kk = 0; kk < 8; kk++) {
        uint32_t af[4];
        af[0] = Ps[(w * 16 + l4) * KS_W + kk * 8 + lm4];
        af[1] = Ps[(w * 16 + l4 + 8) * KS_W + kk * 8 + lm4];
        af[2] = Ps[(w * 16 + l4) * KS_W + kk * 8 + lm4 + 4];
        af[3] = Ps[(w * 16 + l4 + 8) * KS_W + kk * 8 + lm4 + 4];
#pragma unroll
        for (int j = 0; j < 8; j++) {
          uint32_t bf[2];
          bf[0] = Vs[(kk * 8 + lm4) * VS_W + j * 8 + l4];
          bf[1] = Vs[(kk * 8 + lm4 + 4) * VS_W + j * 8 + l4];
          mma_tf32(oacc[j], af, bf);
        }
      }
      __syncwarp();
    }
    __syncthreads();
  }

#pragma unroll
  for (int rh = 0; rh < 2; rh++) {
    const float inv = 1.f / l_i[rh];
    const int r = qb * 128 + w * 16 + l4 + rh * 8;
    float* dst = O + r * C_MODEL + h * DHEAD + 2 * lm4;
#pragma unroll
    for (int j = 0; j < 8; j++) {
      float2 o = make_float2(oacc[j][rh * 2] * inv, oacc[j][rh * 2 + 1] * inv);
      *(float2*)(dst + j * 8) = o;
    }
  }
}

// ---------------------------------------------------------------------------
extern "C" void kernel_launch(void* const* d_in, const int* in_sizes, int n_in,
                              void* d_out, int out_size) {
  const float* x  = (const float*)d_in[0];
  const float* Wq = (const float*)d_in[1];
  const float* bq = (const float*)d_in[2];
  const float* Wk = (const float*)d_in[3];
  const float* bk = (const float*)d_in[4];
  const float* Wv = (const float*)d_in[5];
  const float* bv = (const float*)d_in[6];
  const float* Wo = (const float*)d_in[7];
  const float* bo = (const float*)d_in[8];
  float* out = (float*)d_out;

  float *qp, *kp, *vp, *ap;
  cudaGetSymbolAddress((void**)&qp, g_q);
  cudaGetSymbolAddress((void**)&kp, g_k);
  cudaGetSymbolAddress((void**)&vp, g_v);
  cudaGetSymbolAddress((void**)&ap, g_attn);

  cudaFuncSetAttribute(flash_attn_tc, cudaFuncAttributeMaxDynamicSharedMemorySize,
                       (int)ATTN_SMEM);

  dim3 gqkv(C_MODEL / 128, T_SEQ / 128, 3);  // (8, 32, 3) — one launch
  gemm_qkv<<<gqkv, 256>>>(x, Wq, bq, qp, Wk, bk, kp, Wv, bv, vp);

  dim3 ga(T_SEQ / 128, NHEADS);              // (32, 16)
  flash_attn_tc<<<ga, 256, ATTN_SMEM>>>(qp, kp, vp, ap);

  dim3 gb(C_MODEL / 128, T_SEQ / 128);       // (8, 32)
  gemm_out<<<gb, 256>>>(ap, Wo, bo, out);
}

// round 13
// speedup vs baseline: 1.9484x; 1.0162x over previous
#include <cuda_runtime.h>
#include <math.h>
#include <stdint.h>

#define T_SEQ 4096
#define C_MODEL 1024
#define NHEADS 16
#define DHEAD 64

// Scratch (allocation-free rule: __device__ globals)
__device__ float g_q[T_SEQ * C_MODEL];
__device__ float g_k[T_SEQ * C_MODEL];
__device__ float g_v[T_SEQ * C_MODEL];
__device__ float g_attn[T_SEQ * C_MODEL];

__device__ __forceinline__ uint32_t f2tf32(float x) {
  uint32_t r;
  asm("cvt.rna.tf32.f32 %0, %1;" : "=r"(r) : "f"(x));
  return r;
}

__device__ __forceinline__ void mma_tf32(float* d, const uint32_t* a,
                                         const uint32_t* b) {
  asm volatile(
      "mma.sync.aligned.m16n8k8.row.col.f32.tf32.tf32.f32 "
      "{%0,%1,%2,%3}, {%4,%5,%6,%7}, {%8,%9}, {%0,%1,%2,%3};\n"
      : "+f"(d[0]), "+f"(d[1]), "+f"(d[2]), "+f"(d[3])
      : "r"(a[0]), "r"(a[1]), "r"(a[2]), "r"(a[3]), "r"(b[0]), "r"(b[1]));
}

__device__ __forceinline__ void cp16(uint32_t smem_addr, const void* gptr) {
  asm volatile("cp.async.cg.shared.global [%0], [%1], 16;" ::"r"(smem_addr),
               "l"(gptr));
}
#define CP_COMMIT() asm volatile("cp.async.commit_group;")
#define CP_WAIT0() asm volatile("cp.async.wait_group 0;" ::: "memory")

// ---------------------------------------------------------------------------
// Shared tf32 GEMM body (mma.sync): C[M,N] = A[M,K] @ B[N,K]^T + bias[N]
// CTA tile 128x128, BK=32, 8 warps (2m x 4n), warp tile 64x32.  (R10 proven)
// ---------------------------------------------------------------------------
#define TPITCH 36

template <bool ROUND>
__device__ __forceinline__ void gemm_body(
    const float* __restrict__ A, const float* __restrict__ B,
    const float* __restrict__ bias, float* __restrict__ Cout,
    int M, int N, int K, int bm, int bn) {
  __shared__ uint32_t As[128][TPITCH];
  __shared__ uint32_t Bs[128][TPITCH];

  const int tid = threadIdx.x;
  const int lane = tid & 31;
  const int wid = tid >> 5;
  const int wm = wid >> 2;
  const int wn = wid & 3;
  const int l4 = lane >> 2;
  const int lm4 = lane & 3;

  const int srow = tid >> 1;
  const int scol = (tid & 1) * 16;

  float acc[4][4][4];
#pragma unroll
  for (int i = 0; i < 4; i++)
#pragma unroll
    for (int j = 0; j < 4; j++)
#pragma unroll
      for (int c = 0; c < 4; c++) acc[i][j][c] = 0.f;

  const float* Aptr = A + (bm + srow) * K + scol;
  const float* Bptr = B + (bn + srow) * K + scol;

  float4 pa[4], pb[4];
#pragma unroll
  for (int i = 0; i < 4; i++) {
    pa[i] = *(const float4*)(Aptr + i * 4);
    pb[i] = *(const float4*)(Bptr + i * 4);
  }

  for (int k0 = 0; k0 < K; k0 += 32) {
    __syncthreads();
#pragma unroll
    for (int i = 0; i < 4; i++) {
      uint32_t* ad = &As[srow][scol + i * 4];
      ad[0] = f2tf32(pa[i].x); ad[1] = f2tf32(pa[i].y);
      ad[2] = f2tf32(pa[i].z); ad[3] = f2tf32(pa[i].w);
      uint32_t* bd = &Bs[srow][scol + i * 4];
      bd[0] = f2tf32(pb[i].x); bd[1] = f2tf32(pb[i].y);
      bd[2] = f2tf32(pb[i].z); bd[3] = f2tf32(pb[i].w);
    }
    __syncthreads();

    if (k0 + 32 < K) {
#pragma unroll
      for (int i = 0; i < 4; i++) {
        pa[i] = *(const float4*)(Aptr + k0 + 32 + i * 4);
        pb[i] = *(const float4*)(Bptr + k0 + 32 + i * 4);
      }
    }

#pragma unroll
    for (int kk = 0; kk < 4; kk++) {
      uint32_t af[4][4], bf[4][2];
#pragma unroll
      for (int i = 0; i < 4; i++) {
        const int r = wm * 64 + i * 16 + l4;
        af[i][0] = As[r][kk * 8 + lm4];
        af[i][1] = As[r + 8][kk * 8 + lm4];
        af[i][2] = As[r][kk * 8 + lm4 + 4];
        af[i][3] = As[r + 8][kk * 8 + lm4 + 4];
      }
#pragma unroll
      for (int j = 0; j < 4; j++) {
        const int n = wn * 32 + j * 8 + l4;
        bf[j][0] = Bs[n][kk * 8 + lm4];
        bf[j][1] = Bs[n][kk * 8 + lm4 + 4];
      }
#pragma unroll
      for (int i = 0; i < 4; i++)
#pragma unroll
        for (int j = 0; j < 4; j++) mma_tf32(acc[i][j], af[i], bf[j]);
    }
  }

#pragma unroll
  for (int j = 0; j < 4; j++) {
    const int c = bn + wn * 32 + j * 8 + lm4 * 2;
    const float bi0 = bias[c], bi1 = bias[c + 1];
#pragma unroll
    for (int i = 0; i < 4; i++) {
      const int r = bm + wm * 64 + i * 16 + l4;
      float v00 = acc[i][j][0] + bi0, v01 = acc[i][j][1] + bi1;
      float v10 = acc[i][j][2] + bi0, v11 = acc[i][j][3] + bi1;
      if (ROUND) {
        v00 = __uint_as_float(f2tf32(v00));
        v01 = __uint_as_float(f2tf32(v01));
        v10 = __uint_as_float(f2tf32(v10));
        v11 = __uint_as_float(f2tf32(v11));
      }
      *(float2*)(Cout + r * N + c) = make_float2(v00, v01);
      *(float2*)(Cout + (r + 8) * N + c) = make_float2(v10, v11);
    }
  }
}

// Fused Q/K/V projection: one launch, blockIdx.z selects weight/bias/dst.
__global__ __launch_bounds__(256) void gemm_qkv(
    const float* __restrict__ x,
    const float* __restrict__ Wq, const float* __restrict__ bq,
    float* __restrict__ q,
    const float* __restrict__ Wk, const float* __restrict__ bk,
    float* __restrict__ k,
    const float* __restrict__ Wv, const float* __restrict__ bv,
    float* __restrict__ v) {
  const float* B;
  const float* bias;
  float* out;
  if (blockIdx.z == 0) { B = Wq; bias = bq; out = q; }
  else if (blockIdx.z == 1) { B = Wk; bias = bk; out = k; }
  else { B = Wv; bias = bv; out = v; }
  gemm_body<true>(x, B, bias, out, T_SEQ, C_MODEL, C_MODEL,
                  blockIdx.y * 128, blockIdx.x * 128);
}

__global__ __launch_bounds__(256) void gemm_out(
    const float* __restrict__ A, const float* __restrict__ B,
    const float* __restrict__ bias, float* __restrict__ Cout) {
  gemm_body<false>(A, B, bias, Cout, T_SEQ, C_MODEL, C_MODEL,
                   blockIdx.y * 128, blockIdx.x * 128);
}

// ---------------------------------------------------------------------------
// Causal flash attention on tf32 mma.sync, SOFTWARE-PIPELINED across tiles:
//   iter kt: [stage kt+1] -> softmax(kt)  (scores computed LAST iter; no
//   MMA-wait stall) -> [wait] -> S(kt+1) MMAs -> PV(kt) MMAs.
// K/V double-buffered via cp.async; numerics identical to R10.
// ---------------------------------------------------------------------------
#define KS_W 68
#define VS_W 76
#define SM_KS 0
#define SM_VS (2 * 64 * KS_W)
#define SM_PS (SM_VS + 2 * 64 * VS_W)
#define ATTN_WORDS (SM_PS + 128 * KS_W)
#define ATTN_SMEM (ATTN_WORDS * sizeof(uint32_t))  // 108,544 B

__global__ __launch_bounds__(256, 2) void flash_attn_tc(
    const float* __restrict__ Q, const float* __restrict__ K,
    const float* __restrict__ V, float* __restrict__ O) {
  extern __shared__ uint32_t smu[];
  const uint32_t sbase = (uint32_t)__cvta_generic_to_shared(smu);
  uint32_t* Ps = smu + SM_PS;  // [128][KS_W]

  const int qb = gridDim.x - 1 - blockIdx.x;  // heavy q-blocks first
  const int h  = blockIdx.y;
  const int tid = threadIdx.x;
  const int lane = tid & 31;
  const int w = tid >> 5;
  const int l4 = lane >> 2;
  const int lm4 = lane & 3;
  const float scale2 = 0.125f * 1.44269504088896f;
  const int nkt = 2 * qb + 2;
  const int wrow_last = qb * 128 + w * 16 + 15;

#define ASTAGE(t, b)                                                          \
  do {                                                                        \
    _Pragma("unroll") for (int i_ = 0; i_ < 4; i_++) {                        \
      const int c_ = tid + i_ * 256;                                          \
      const int row_ = c_ >> 4, col4_ = (c_ & 15) << 2;                       \
      cp16(sbase + (SM_KS + (b) * 64 * KS_W + row_ * KS_W + col4_) * 4,       \
           K + ((t) * 64 + row_) * C_MODEL + h * DHEAD + col4_);              \
      cp16(sbase + (SM_VS + (b) * 64 * VS_W + row_ * VS_W + col4_) * 4,       \
           V + ((t) * 64 + row_) * C_MODEL + h * DHEAD + col4_);              \
    }                                                                         \
    CP_COMMIT();                                                              \
  } while (0)

  ASTAGE(0, 0);  // tile 0 in flight

  // stage Q [128][64] (tf32-rounded at production) into Ps
  {
    const int r = tid >> 1;
    const int cb = (tid & 1) * 32;
    const uint32_t* src =
        (const uint32_t*)(Q + (qb * 128 + r) * C_MODEL + h * DHEAD + cb);
#pragma unroll
    for (int i = 0; i < 8; i++) {
      uint4 v4 = *(const uint4*)(src + i * 4);
      uint32_t* d = &Ps[r * KS_W + cb + i * 4];
      d[0] = v4.x; d[1] = v4.y; d[2] = v4.z; d[3] = v4.w;
    }
  }
  __syncthreads();

  uint32_t qf[8][4];
  {
    const int m0 = w * 16;
#pragma unroll
    for (int kk = 0; kk < 8; kk++) {
      qf[kk][0] = Ps[(m0 + l4) * KS_W + kk * 8 + lm4];
      qf[kk][1] = Ps[(m0 + l4 + 8) * KS_W + kk * 8 + lm4];
      qf[kk][2] = Ps[(m0 + l4) * KS_W + kk * 8 + lm4 + 4];
      qf[kk][3] = Ps[(m0 + l4 + 8) * KS_W + kk * 8 + lm4 + 4];
    }
  }

  float m_i[2] = {-1e30f, -1e30f};
  float l_i[2] = {0.f, 0.f};
  float oacc[8][4];
#pragma unroll
  for (int j = 0; j < 8; j++)
#pragma unroll
    for (int c = 0; c < 4; c++) oacc[j][c] = 0.f;

  float sc[8][4];  // scores for the tile whose softmax runs NEXT iteration

  // wait tile 0, then compute S(0)
  CP_WAIT0();
  __syncthreads();
  {
    const uint32_t* Ks = smu + SM_KS;  // buf 0
#pragma unroll
    for (int j = 0; j < 8; j++)
#pragma unroll
      for (int c = 0; c < 4; c++) sc[j][c] = 0.f;
#pragma unroll
    for (int kk = 0; kk < 8; kk++) {
#pragma unroll
      for (int j = 0; j < 8; j++) {
        uint32_t bf[2];
        bf[0] = Ks[(j * 8 + l4) * KS_W + kk * 8 + lm4];
        bf[1] = Ks[(j * 8 + l4) * KS_W + kk * 8 + lm4 + 4];
        mma_tf32(sc[j], qf[kk], bf);
      }
    }
  }

  for (int kt = 0; kt < nkt; kt++) {
    const bool active = (kt * 64 <= wrow_last);

    __syncthreads();  // buf (kt+1)&1 free: S(kt-1)/PV(kt-1) readers done
    if (kt + 1 < nkt) ASTAGE(kt + 1, (kt + 1) & 1);

    // ---- softmax(kt): consumes sc computed last iteration (no MMA stall) --
    if (active) {
      if (kt >= 2 * qb) {  // diagonal tile: mask + scale
        const int r0 = qb * 128 + w * 16 + l4;
#pragma unroll
        for (int j = 0; j < 8; j++) {
          const int c0 = kt * 64 + j * 8 + 2 * lm4;
          sc[j][0] = (c0 > r0) ? -1e30f : sc[j][0] * scale2;
          sc[j][1] = (c0 + 1 > r0) ? -1e30f : sc[j][1] * scale2;
          sc[j][2] = (c0 > r0 + 8) ? -1e30f : sc[j][2] * scale2;
          sc[j][3] = (c0 + 1 > r0 + 8) ? -1e30f : sc[j][3] * scale2;
        }
      } else {
#pragma unroll
        for (int j = 0; j < 8; j++)
#pragma unroll
          for (int c = 0; c < 4; c++) sc[j][c] *= scale2;
      }

#pragma unroll
      for (int rh = 0; rh < 2; rh++) {
        const int cb = rh * 2;
        float rm = sc[0][cb];
#pragma unroll
        for (int j = 0; j < 8; j++)
          rm = fmaxf(rm, fmaxf(sc[j][cb], sc[j][cb + 1]));
        rm = fmaxf(rm, __shfl_xor_sync(0xffffffffu, rm, 1));
        rm = fmaxf(rm, __shfl_xor_sync(0xffffffffu, rm, 2));
        const float mnew = fmaxf(m_i[rh], rm);
        const float alpha = exp2f(m_i[rh] - mnew);
        float rs = 0.f;
#pragma unroll
        for (int j = 0; j < 8; j++) {
          const float p0 = exp2f(sc[j][cb] - mnew);
          const float p1 = exp2f(sc[j][cb + 1] - mnew);
          sc[j][cb] = p0; sc[j][cb + 1] = p1;
          rs += p0 + p1;
        }
        rs += __shfl_xor_sync(0xffffffffu, rs, 1);
        rs += __shfl_xor_sync(0xffffffffu, rs, 2);
        l_i[rh] = l_i[rh] * alpha + rs;
        m_i[rh] = mnew;
#pragma unroll
        for (int j = 0; j < 8; j++) {
          oacc[j][cb] *= alpha;
          oacc[j][cb + 1] *= alpha;
        }
        const int pr = (w * 16 + l4 + rh * 8) * KS_W + 2 * lm4;
#pragma unroll
        for (int j = 0; j < 8; j++) {
          uint2 pp = make_uint2(f2tf32(sc[j][cb]), f2tf32(sc[j][cb + 1]));
          *(uint2*)&Ps[pr + j * 8] = pp;
        }
      }
    }

    CP_WAIT0();       // tile kt+1 landed (this thread's copies)
    __syncthreads();  // ... and everyone else's

    // ---- S(kt+1): fresh scores into sc (consumed next iteration) ----------
    if (kt + 1 < nkt && (kt + 1) * 64 <= wrow_last) {
      const uint32_t* Ks = smu + SM_KS + ((kt + 1) & 1) * 64 * KS_W;
#pragma unroll
      for (int j = 0; j < 8; j++)
#pragma unroll
        for (int c = 0; c < 4; c++) sc[j][c] = 0.f;
#pragma unroll
      for (int kk = 0; kk < 8; kk++) {
#pragma unroll
        for (int j = 0; j < 8; j++) {
          uint32_t bf[2];
          bf[0] = Ks[(j * 8 + l4) * KS_W + kk * 8 + lm4];
          bf[1] = Ks[(j * 8 + l4) * KS_W + kk * 8 + lm4 + 4];
          mma_tf32(sc[j], qf[kk], bf);
        }
      }
    }

    // ---- PV(kt) ------------------------------------------------------------
    if (active) {
      const uint32_t* Vs = smu + SM_VS + (kt & 1) * 64 * VS_W;
#pragma unroll
      for (int kk = 0; kk < 8; kk++) {
        uint32_t af[4];
        af[0] = Ps[(w * 16 + l4) * KS_W + kk * 8 + lm4];
        af[1] = Ps[(w * 16 + l4 + 8) * KS_W + kk * 8 + lm4];
        af[2] = Ps[(w * 16 + l4) * KS_W + kk * 8 + lm4 + 4];
        af[3] = Ps[(w * 16 + l4 + 8) * KS_W + kk * 8 + lm4 + 4];
#pragma unroll
        for (int j = 0; j < 8; j++) {
          uint32_t bf[2];
          bf[0] = Vs[(kk * 8 + lm4) * VS_W + j * 8 + l4];
          bf[1] = Vs[(kk * 8 + lm4 + 4) * VS_W + j * 8 + l4];
          mma_tf32(oacc[j], af, bf);
        }
      }
    }
  }

  // ---- epilogue: normalize, store [T, C] head-interleaved ----
#pragma unroll
  for (int rh = 0; rh < 2; rh++) {
    const float inv = 1.f / l_i[rh];
    const int r = qb * 128 + w * 16 + l4 + rh * 8;
    float* dst = O + r * C_MODEL + h * DHEAD + 2 * lm4;
#pragma unroll
    for (int j = 0; j < 8; j++) {
      float2 o = make_float2(oacc[j][rh * 2] * inv, oacc[j][rh * 2 + 1] * inv);
      *(float2*)(dst + j * 8) = o;
    }
  }
#undef ASTAGE
}

// ---------------------------------------------------------------------------
extern "C" void kernel_launch(void* const* d_in, const int* in_sizes, int n_in,
                              void* d_out, int out_size) {
  const float* x  = (const float*)d_in[0];
  const float* Wq = (const float*)d_in[1];
  const float* bq = (const float*)d_in[2];
  const float* Wk = (const float*)d_in[3];
  const float* bk = (const float*)d_in[4];
  const float* Wv = (const float*)d_in[5];
  const float* bv = (const float*)d_in[6];
  const float* Wo = (const float*)d_in[7];
  const float* bo = (const float*)d_in[8];
  float* out = (float*)d_out;

  float *qp, *kp, *vp, *ap;
  cudaGetSymbolAddress((void**)&qp, g_q);
  cudaGetSymbolAddress((void**)&kp, g_k);
  cudaGetSymbolAddress((void**)&vp, g_v);
  cudaGetSymbolAddress((void**)&ap, g_attn);

  cudaFuncSetAttribute(flash_attn_tc, cudaFuncAttributeMaxDynamicSharedMemorySize,
                       (int)ATTN_SMEM);

  dim3 gqkv(C_MODEL / 128, T_SEQ / 128, 3);  // (8, 32, 3)
  gemm_qkv<<<gqkv, 256>>>(x, Wq, bq, qp, Wk, bk, kp, Wv, bv, vp);

  dim3 ga(T_SEQ / 128, NHEADS);              // (32, 16)
  flash_attn_tc<<<ga, 256, ATTN_SMEM>>>(qp, kp, vp, ap);

  dim3 gb(C_MODEL / 128, T_SEQ / 128);       // (8, 32)
  gemm_out<<<gb, 256>>>(ap, Wo, bo, out);
}

// round 15
// speedup vs baseline: 2.2953x; 1.1781x over previous
#include <cuda_runtime.h>
#include <math.h>
#include <stdint.h>

#define T_SEQ 4096
#define C_MODEL 1024
#define NHEADS 16
#define DHEAD 64

// Scratch (allocation-free rule: __device__ globals)
__device__ float g_q[T_SEQ * C_MODEL];
__device__ float g_k[T_SEQ * C_MODEL];
__device__ float g_v[T_SEQ * C_MODEL];
__device__ float g_attn[T_SEQ * C_MODEL];

__device__ __forceinline__ uint32_t f2tf32(float x) {
  uint32_t r;
  asm("cvt.rna.tf32.f32 %0, %1;" : "=r"(r) : "f"(x));
  return r;
}

__device__ __forceinline__ void mma_tf32(float* d, const uint32_t* a,
                                         const uint32_t* b) {
  asm volatile(
      "mma.sync.aligned.m16n8k8.row.col.f32.tf32.tf32.f32 "
      "{%0,%1,%2,%3}, {%4,%5,%6,%7}, {%8,%9}, {%0,%1,%2,%3};\n"
      : "+f"(d[0]), "+f"(d[1]), "+f"(d[2]), "+f"(d[3])
      : "r"(a[0]), "r"(a[1]), "r"(a[2]), "r"(a[3]), "r"(b[0]), "r"(b[1]));
}

__device__ __forceinline__ void cp16(uint32_t smem_addr, const void* gptr) {
  asm volatile("cp.async.cg.shared.global [%0], [%1], 16;" ::"r"(smem_addr),
               "l"(gptr));
}
#define CP_COMMIT() asm volatile("cp.async.commit_group;")
#define CP_WAIT0() asm volatile("cp.async.wait_group 0;" ::: "memory")

// ---------------------------------------------------------------------------
// Shared tf32 GEMM body (mma.sync): C[M,N] = A[M,K] @ B[N,K]^T + bias[N]
// CTA tile 128x128, BK=32, 8 warps (2m x 4n), warp tile 64x32.  (unchanged)
// ---------------------------------------------------------------------------
#define TPITCH 36

template <bool ROUND>
__device__ __forceinline__ void gemm_body(
    const float* __restrict__ A, const float* __restrict__ B,
    const float* __restrict__ bias, float* __restrict__ Cout,
    int M, int N, int K, int bm, int bn) {
  __shared__ uint32_t As[128][TPITCH];
  __shared__ uint32_t Bs[128][TPITCH];

  const int tid = threadIdx.x;
  const int lane = tid & 31;
  const int wid = tid >> 5;
  const int wm = wid >> 2;
  const int wn = wid & 3;
  const int l4 = lane >> 2;
  const int lm4 = lane & 3;

  const int srow = tid >> 1;
  const int scol = (tid & 1) * 16;

  float acc[4][4][4];
#pragma unroll
  for (int i = 0; i < 4; i++)
#pragma unroll
    for (int j = 0; j < 4; j++)
#pragma unroll
      for (int c = 0; c < 4; c++) acc[i][j][c] = 0.f;

  const float* Aptr = A + (bm + srow) * K + scol;
  const float* Bptr = B + (bn + srow) * K + scol;

  float4 pa[4], pb[4];
#pragma unroll
  for (int i = 0; i < 4; i++) {
    pa[i] = *(const float4*)(Aptr + i * 4);
    pb[i] = *(const float4*)(Bptr + i * 4);
  }

  for (int k0 = 0; k0 < K; k0 += 32) {
    __syncthreads();
#pragma unroll
    for (int i = 0; i < 4; i++) {
      uint32_t* ad = &As[srow][scol + i * 4];
      ad[0] = f2tf32(pa[i].x); ad[1] = f2tf32(pa[i].y);
      ad[2] = f2tf32(pa[i].z); ad[3] = f2tf32(pa[i].w);
      uint32_t* bd = &Bs[srow][scol + i * 4];
      bd[0] = f2tf32(pb[i].x); bd[1] = f2tf32(pb[i].y);
      bd[2] = f2tf32(pb[i].z); bd[3] = f2tf32(pb[i].w);
    }
    __syncthreads();

    if (k0 + 32 < K) {
#pragma unroll
      for (int i = 0; i < 4; i++) {
        pa[i] = *(const float4*)(Aptr + k0 + 32 + i * 4);
        pb[i] = *(const float4*)(Bptr + k0 + 32 + i * 4);
      }
    }

#pragma unroll
    for (int kk = 0; kk < 4; kk++) {
      uint32_t af[4][4], bf[4][2];
#pragma unroll
      for (int i = 0; i < 4; i++) {
        const int r = wm * 64 + i * 16 + l4;
        af[i][0] = As[r][kk * 8 + lm4];
        af[i][1] = As[r + 8][kk * 8 + lm4];
        af[i][2] = As[r][kk * 8 + lm4 + 4];
        af[i][3] = As[r + 8][kk * 8 + lm4 + 4];
      }
#pragma unroll
      for (int j = 0; j < 4; j++) {
        const int n = wn * 32 + j * 8 + l4;
        bf[j][0] = Bs[n][kk * 8 + lm4];
        bf[j][1] = Bs[n][kk * 8 + lm4 + 4];
      }
#pragma unroll
      for (int i = 0; i < 4; i++)
#pragma unroll
        for (int j = 0; j < 4; j++) mma_tf32(acc[i][j], af[i], bf[j]);
    }
  }

#pragma unroll
  for (int j = 0; j < 4; j++) {
    const int c = bn + wn * 32 + j * 8 + lm4 * 2;
    const float bi0 = bias[c], bi1 = bias[c + 1];
#pragma unroll
    for (int i = 0; i < 4; i++) {
      const int r = bm + wm * 64 + i * 16 + l4;
      float v00 = acc[i][j][0] + bi0, v01 = acc[i][j][1] + bi1;
      float v10 = acc[i][j][2] + bi0, v11 = acc[i][j][3] + bi1;
      if (ROUND) {
        v00 = __uint_as_float(f2tf32(v00));
        v01 = __uint_as_float(f2tf32(v01));
        v10 = __uint_as_float(f2tf32(v10));
        v11 = __uint_as_float(f2tf32(v11));
      }
      *(float2*)(Cout + r * N + c) = make_float2(v00, v01);
      *(float2*)(Cout + (r + 8) * N + c) = make_float2(v10, v11);
    }
  }
}

__global__ __launch_bounds__(256) void gemm_qkv(
    const float* __restrict__ x,
    const float* __restrict__ Wq, const float* __restrict__ bq,
    float* __restrict__ q,
    const float* __restrict__ Wk, const float* __restrict__ bk,
    float* __restrict__ k,
    const float* __restrict__ Wv, const float* __restrict__ bv,
    float* __restrict__ v) {
  const float* B;
  const float* bias;
  float* out;
  if (blockIdx.z == 0) { B = Wq; bias = bq; out = q; }
  else if (blockIdx.z == 1) { B = Wk; bias = bk; out = k; }
  else { B = Wv; bias = bv; out = v; }
  gemm_body<true>(x, B, bias, out, T_SEQ, C_MODEL, C_MODEL,
                  blockIdx.y * 128, blockIdx.x * 128);
}

__global__ __launch_bounds__(256) void gemm_out(
    const float* __restrict__ A, const float* __restrict__ B,
    const float* __restrict__ bias, float* __restrict__ Cout) {
  gemm_body<false>(A, B, bias, Cout, T_SEQ, C_MODEL, C_MODEL,
                   blockIdx.y * 128, blockIdx.x * 128);
}

// ---------------------------------------------------------------------------
// Causal flash attention, tf32 mma.sync, warp M-tile = 32 q-rows.
// CTA: 128 q-rows x 1 head, 4 warps (128 thr), 2 CTAs/SM.
// K/V fragments loaded once per (kk,j) and reused by both m-subtiles.
// Pipeline per tile: stage(kt+1) -> softmax(kt) -> PV(kt) -> wait -> S(kt+1).
// ---------------------------------------------------------------------------
#define KS_W 68
#define VS_W 76
#define SM_KS 0
#define SM_VS (2 * 64 * KS_W)
#define SM_PS (SM_VS + 2 * 64 * VS_W)
#define ATTN_WORDS (SM_PS + 128 * KS_W)
#define ATTN_SMEM (ATTN_WORDS * sizeof(uint32_t))  // 108,544 B

__global__ __launch_bounds__(128, 2) void flash_attn_tc(
    const float* __restrict__ Q, const float* __restrict__ K,
    const float* __restrict__ V, float* __restrict__ O) {
  extern __shared__ uint32_t smu[];
  const uint32_t sbase = (uint32_t)__cvta_generic_to_shared(smu);
  uint32_t* Ps = smu + SM_PS;  // [128][KS_W] (Q stage, then P tiles)

  const int qb = gridDim.x - 1 - blockIdx.x;  // heavy q-blocks first
  const int h  = blockIdx.y;
  const int tid = threadIdx.x;
  const int lane = tid & 31;
  const int w = tid >> 5;      // 0..3
  const int l4 = lane >> 2;    // 0..7
  const int lm4 = lane & 3;    // 0..3
  const float scale2 = 0.125f * 1.44269504088896f;  // 1/sqrt(64)*log2(e)
  const int nkt = 2 * qb + 2;
  const int wrow_last = qb * 128 + w * 32 + 31;

// stage K/V tile t into buffer b: 1024 16B-chunks each, 128 threads x 8
#define ASTAGE(t, b)                                                          \
  do {                                                                        \
    _Pragma("unroll") for (int i_ = 0; i_ < 8; i_++) {                        \
      const int c_ = tid + i_ * 128;                                          \
      const int row_ = c_ >> 4, col4_ = (c_ & 15) << 2;                       \
      cp16(sbase + (SM_KS + (b) * 64 * KS_W + row_ * KS_W + col4_) * 4,       \
           K + ((t) * 64 + row_) * C_MODEL + h * DHEAD + col4_);              \
      cp16(sbase + (SM_VS + (b) * 64 * VS_W + row_ * VS_W + col4_) * 4,       \
           V + ((t) * 64 + row_) * C_MODEL + h * DHEAD + col4_);              \
    }                                                                         \
    CP_COMMIT();                                                              \
  } while (0)

  ASTAGE(0, 0);

  // stage Q [128][64] into Ps: 1 row per thread, FULL 64 words (16 x uint4)
  {
    const uint32_t* src =
        (const uint32_t*)(Q + (qb * 128 + tid) * C_MODEL + h * DHEAD);
#pragma unroll
    for (int i = 0; i < 16; i++) {
      uint4 v4 = *(const uint4*)(src + i * 4);
      uint32_t* d = &Ps[tid * KS_W + i * 4];
      d[0] = v4.x; d[1] = v4.y; d[2] = v4.z; d[3] = v4.w;
    }
  }
  __syncthreads();

  // persistent Q fragments: 2 m-subtiles x 8 kk x 4 regs
  uint32_t qf[2][8][4];
#pragma unroll
  for (int t = 0; t < 2; t++) {
    const int m0 = w * 32 + t * 16;
#pragma unroll
    for (int kk = 0; kk < 8; kk++) {
      qf[t][kk][0] = Ps[(m0 + l4) * KS_W + kk * 8 + lm4];
      qf[t][kk][1] = Ps[(m0 + l4 + 8) * KS_W + kk * 8 + lm4];
      qf[t][kk][2] = Ps[(m0 + l4) * KS_W + kk * 8 + lm4 + 4];
      qf[t][kk][3] = Ps[(m0 + l4 + 8) * KS_W + kk * 8 + lm4 + 4];
    }
  }

  float m_i[2][2], l_i[2][2];
  float oacc[2][8][4];
#pragma unroll
  for (int t = 0; t < 2; t++)
#pragma unroll
    for (int rh = 0; rh < 2; rh++) { m_i[t][rh] = -1e30f; l_i[t][rh] = 0.f; }
#pragma unroll
  for (int t = 0; t < 2; t++)
#pragma unroll
    for (int j = 0; j < 8; j++)
#pragma unroll
      for (int c = 0; c < 4; c++) oacc[t][j][c] = 0.f;

  float sc[2][8][4];  // scores: softmaxed one iteration later

  // tile 0 resident, compute S(0)
  CP_WAIT0();
  __syncthreads();
  {
    const uint32_t* Ks = smu + SM_KS;
#pragma unroll
    for (int t = 0; t < 2; t++)
#pragma unroll
      for (int j = 0; j < 8; j++)
#pragma unroll
        for (int c = 0; c < 4; c++) sc[t][j][c] = 0.f;
#pragma unroll
    for (int kk = 0; kk < 8; kk++) {
#pragma unroll
      for (int j = 0; j < 8; j++) {
        uint32_t bf[2];
        bf[0] = Ks[(j * 8 + l4) * KS_W + kk * 8 + lm4];
        bf[1] = Ks[(j * 8 + l4) * KS_W + kk * 8 + lm4 + 4];
        mma_tf32(sc[0][j], qf[0][kk], bf);
        mma_tf32(sc[1][j], qf[1][kk], bf);
      }
    }
  }

  for (int kt = 0; kt < nkt; kt++) {
    const bool active = (kt * 64 <= wrow_last);

    if (kt + 1 < nkt) ASTAGE(kt + 1, (kt + 1) & 1);

    // ---- softmax(kt) on sc (scores from last iteration; no MMA stall) ----
    if (active) {
      if (kt >= 2 * qb) {  // diagonal region: mask + scale
#pragma unroll
        for (int t = 0; t < 2; t++) {
          const int r0 = qb * 128 + w * 32 + t * 16 + l4;
#pragma unroll
          for (int j = 0; j < 8; j++) {
            const int c0 = kt * 64 + j * 8 + 2 * lm4;
            sc[t][j][0] = (c0 > r0) ? -1e30f : sc[t][j][0] * scale2;
            sc[t][j][1] = (c0 + 1 > r0) ? -1e30f : sc[t][j][1] * scale2;
            sc[t][j][2] = (c0 > r0 + 8) ? -1e30f : sc[t][j][2] * scale2;
            sc[t][j][3] = (c0 + 1 > r0 + 8) ? -1e30f : sc[t][j][3] * scale2;
          }
        }
      } else {
#pragma unroll
        for (int t = 0; t < 2; t++)
#pragma unroll
          for (int j = 0; j < 8; j++)
#pragma unroll
            for (int c = 0; c < 4; c++) sc[t][j][c] *= scale2;
      }

#pragma unroll
      for (int t = 0; t < 2; t++) {
#pragma unroll
        for (int rh = 0; rh < 2; rh++) {
          const int cb = rh * 2;
          float rm = sc[t][0][cb];
#pragma unroll
          for (int j = 0; j < 8; j++)
            rm = fmaxf(rm, fmaxf(sc[t][j][cb], sc[t][j][cb + 1]));
          rm = fmaxf(rm, __shfl_xor_sync(0xffffffffu, rm, 1));
          rm = fmaxf(rm, __shfl_xor_sync(0xffffffffu, rm, 2));
          const float mnew = fmaxf(m_i[t][rh], rm);
          const float alpha = exp2f(m_i[t][rh] - mnew);
          float rs = 0.f;
#pragma unroll
          for (int j = 0; j < 8; j++) {
            const float p0 = exp2f(sc[t][j][cb] - mnew);
            const float p1 = exp2f(sc[t][j][cb + 1] - mnew);
            sc[t][j][cb] = p0; sc[t][j][cb + 1] = p1;
            rs += p0 + p1;
          }
          rs += __shfl_xor_sync(0xffffffffu, rs, 1);
          rs += __shfl_xor_sync(0xffffffffu, rs, 2);
          l_i[t][rh] = l_i[t][rh] * alpha + rs;
          m_i[t][rh] = mnew;
#pragma unroll
          for (int j = 0; j < 8; j++) {
            oacc[t][j][cb] *= alpha;
            oacc[t][j][cb + 1] *= alpha;
          }
          const int pr = (w * 32 + t * 16 + l4 + rh * 8) * KS_W + 2 * lm4;
#pragma unroll
          for (int j = 0; j < 8; j++) {
            uint2 pp =
                make_uint2(f2tf32(sc[t][j][cb]), f2tf32(sc[t][j][cb + 1]));
            *(uint2*)&Ps[pr + j * 8] = pp;
          }
        }
      }
      __syncwarp();

      // ---- PV(kt): V buffer kt&1 is resident ----
      const uint32_t* Vs = smu + SM_VS + (kt & 1) * 64 * VS_W;
#pragma unroll
      for (int kk = 0; kk < 8; kk++) {
        uint32_t af0[4], af1[4];
        af0[0] = Ps[(w * 32 + l4) * KS_W + kk * 8 + lm4];
        af0[1] = Ps[(w * 32 + l4 + 8) * KS_W + kk * 8 + lm4];
        af0[2] = Ps[(w * 32 + l4) * KS_W + kk * 8 + lm4 + 4];
        af0[3] = Ps[(w * 32 + l4 + 8) * KS_W + kk * 8 + lm4 + 4];
        af1[0] = Ps[(w * 32 + 16 + l4) * KS_W + kk * 8 + lm4];
        af1[1] = Ps[(w * 32 + 24 + l4) * KS_W + kk * 8 + lm4];
        af1[2] = Ps[(w * 32 + 16 + l4) * KS_W + kk * 8 + lm4 + 4];
        af1[3] = Ps[(w * 32 + 24 + l4) * KS_W + kk * 8 + lm4 + 4];
#pragma unroll
        for (int j = 0; j < 8; j++) {
          uint32_t bf[2];
          bf[0] = Vs[(kk * 8 + lm4) * VS_W + j * 8 + l4];
          bf[1] = Vs[(kk * 8 + lm4 + 4) * VS_W + j * 8 + l4];
          mma_tf32(oacc[0][j], af0, bf);
          mma_tf32(oacc[1][j], af1, bf);
        }
      }
      __syncwarp();
    }

    CP_WAIT0();       // tile kt+1 landed (this thread)
    __syncthreads();  // ...and all threads; also frees buf for next stage

    // ---- S(kt+1): fresh scores into sc ----
    if (kt + 1 < nkt && (kt + 1) * 64 <= wrow_last) {
      const uint32_t* Ks = smu + SM_KS + ((kt + 1) & 1) * 64 * KS_W;
#pragma unroll
      for (int t = 0; t < 2; t++)
#pragma unroll
        for (int j = 0; j < 8; j++)
#pragma unroll
          for (int c = 0; c < 4; c++) sc[t][j][c] = 0.f;
#pragma unroll
      for (int kk = 0; kk < 8; kk++) {
#pragma unroll
        for (int j = 0; j < 8; j++) {
          uint32_t bf[2];
          bf[0] = Ks[(j * 8 + l4) * KS_W + kk * 8 + lm4];
          bf[1] = Ks[(j * 8 + l4) * KS_W + kk * 8 + lm4 + 4];
          mma_tf32(sc[0][j], qf[0][kk], bf);
          mma_tf32(sc[1][j], qf[1][kk], bf);
        }
      }
    }
  }

  // ---- epilogue: normalize, store [T, C] head-interleaved ----
#pragma unroll
  for (int t = 0; t < 2; t++) {
#pragma unroll
    for (int rh = 0; rh < 2; rh++) {
      const float inv = 1.f / l_i[t][rh];
      const int r = qb * 128 + w * 32 + t * 16 + l4 + rh * 8;
      float* dst = O + r * C_MODEL + h * DHEAD + 2 * lm4;
#pragma unroll
      for (int j = 0; j < 8; j++) {
        float2 o = make_float2(oacc[t][j][rh * 2] * inv,
                               oacc[t][j][rh * 2 + 1] * inv);
        *(float2*)(dst + j * 8) = o;
      }
    }
  }
#undef ASTAGE
}

// ---------------------------------------------------------------------------
extern "C" void kernel_launch(void* const* d_in, const int* in_sizes, int n_in,
                              void* d_out, int out_size) {
  const float* x  = (const float*)d_in[0];
  const float* Wq = (const float*)d_in[1];
  const float* bq = (const float*)d_in[2];
  const float* Wk = (const float*)d_in[3];
  const float* bk = (const float*)d_in[4];
  const float* Wv = (const float*)d_in[5];
  const float* bv = (const float*)d_in[6];
  const float* Wo = (const float*)d_in[7];
  const float* bo = (const float*)d_in[8];
  float* out = (float*)d_out;

  float *qp, *kp, *vp, *ap;
  cudaGetSymbolAddress((void**)&qp, g_q);
  cudaGetSymbolAddress((void**)&kp, g_k);
  cudaGetSymbolAddress((void**)&vp, g_v);
  cudaGetSymbolAddress((void**)&ap, g_attn);

  cudaFuncSetAttribute(flash_attn_tc, cudaFuncAttributeMaxDynamicSharedMemorySize,
                       (int)ATTN_SMEM);

  dim3 gqkv(C_MODEL / 128, T_SEQ / 128, 3);  // (8, 32, 3)
  gemm_qkv<<<gqkv, 256>>>(x, Wq, bq, qp, Wk, bk, kp, Wv, bv, vp);

  dim3 ga(T_SEQ / 128, NHEADS);              // (32, 16)
  flash_attn_tc<<<ga, 128, ATTN_SMEM>>>(qp, kp, vp, ap);

  dim3 gb(C_MODEL / 128, T_SEQ / 128);       // (8, 32)
  gemm_out<<<gb, 256>>>(ap, Wo, bo, out);
}